// round 2
// baseline (speedup 1.0000x reference)
#include <cuda_runtime.h>

#define BB 4
#define SS 2048
#define DD 128
#define CC 128
#define NCH (SS/CC)   // 16 chunks
#define LD 132        // smem row stride (floats), float4-aligned, conflict-free frags

// ------------------- scratch (device globals; no allocs allowed) -------------------
__device__ float g_phiK[BB*SS*DD];          // 4 MB
__device__ float g_phiQ[BB*SS*DD];          // 4 MB
__device__ float g_Sc [BB*NCH*DD*DD];       // 4 MB  per-chunk K^T V
__device__ float g_nc [BB*NCH*DD];          //       per-chunk sum(phiK)
__device__ float g_Mp [BB*NCH*DD*DD];       // 4 MB  exclusive prefix of g_Sc
__device__ float g_Np [BB*NCH*DD];          //       exclusive prefix of g_nc

#define FRAG_LOAD(dst8, ptr) {                                  \
    float4 _v0 = *reinterpret_cast<const float4*>(ptr);         \
    float4 _v1 = *reinterpret_cast<const float4*>((ptr) + 4);   \
    dst8[0]=_v0.x; dst8[1]=_v0.y; dst8[2]=_v0.z; dst8[3]=_v0.w; \
    dst8[4]=_v1.x; dst8[5]=_v1.y; dst8[6]=_v1.z; dst8[7]=_v1.w; }

// ============================================================================
// Kernel 1: phi(X) = exp(-0.5*||x||)/sqrt(128) * exp(X @ W^T)
// grid = 128 blocks (64 row-tiles x {K,Q}), 256 threads
// smem: Xs[d][t] transposed, Ws[d][m] transposed, ssum[128]
// ============================================================================
__global__ void __launch_bounds__(256, 1)
phi_kernel(const float* __restrict__ K, const float* __restrict__ Q,
           const float* __restrict__ W) {
    extern __shared__ float sm[];
    float* Xs   = sm;                 // [128][LD]  Xs[d*LD + t]
    float* Ws   = sm + DD*LD;         // [128][LD]  Ws[d*LD + m]
    float* ssum = sm + 2*DD*LD;       // [128] -> becomes scale[t]

    const int tid     = threadIdx.x;
    const int tileIdx = blockIdx.x & 63;           // 8192 rows / 128 = 64 tiles
    const int sel     = blockIdx.x >> 6;           // 0 = K, 1 = Q
    const float* src  = sel ? Q : K;
    float*       dst  = sel ? g_phiQ : g_phiK;
    const float* Xg   = src + (size_t)tileIdx * 128 * DD;

    if (tid < 128) ssum[tid] = 0.f;
    __syncthreads();

    // transpose-load X (+ squared-sum) and W
    #pragma unroll
    for (int it = 0; it < 16; ++it) {
        int i  = tid + it*256;
        int t  = i >> 5;        // row (constant within a warp)
        int d4 = i & 31;        // float4 column
        float4 v = reinterpret_cast<const float4*>(Xg)[t*32 + d4];
        Xs[(d4*4+0)*LD + t] = v.x;
        Xs[(d4*4+1)*LD + t] = v.y;
        Xs[(d4*4+2)*LD + t] = v.z;
        Xs[(d4*4+3)*LD + t] = v.w;
        float ls = v.x*v.x + v.y*v.y + v.z*v.z + v.w*v.w;
        ls += __shfl_xor_sync(0xffffffffu, ls, 16);
        ls += __shfl_xor_sync(0xffffffffu, ls, 8);
        ls += __shfl_xor_sync(0xffffffffu, ls, 4);
        ls += __shfl_xor_sync(0xffffffffu, ls, 2);
        ls += __shfl_xor_sync(0xffffffffu, ls, 1);
        if ((tid & 31) == 0) atomicAdd(&ssum[t], ls);

        float4 w = reinterpret_cast<const float4*>(W)[t*32 + d4]; // W[m=t][d]
        Ws[(d4*4+0)*LD + t] = w.x;
        Ws[(d4*4+1)*LD + t] = w.y;
        Ws[(d4*4+2)*LD + t] = w.z;
        Ws[(d4*4+3)*LD + t] = w.w;
    }
    __syncthreads();
    if (tid < 128) {
        // scale = exp(-0.5*||x||) / sqrt(128)
        ssum[tid] = __expf(-0.5f * sqrtf(ssum[tid])) * 0.08838834764831845f;
    }
    __syncthreads();

    const int tx = tid & 15, ty = tid >> 4;
    const int t0 = ty*8, m0 = tx*8;
    float acc[8][8];
    #pragma unroll
    for (int i = 0; i < 8; ++i)
        #pragma unroll
        for (int j = 0; j < 8; ++j) acc[i][j] = 0.f;

    #pragma unroll 4
    for (int d = 0; d < 128; ++d) {
        float a[8], b[8];
        FRAG_LOAD(a, &Xs[d*LD + t0]);
        FRAG_LOAD(b, &Ws[d*LD + m0]);
        #pragma unroll
        for (int i = 0; i < 8; ++i)
            #pragma unroll
            for (int j = 0; j < 8; ++j)
                acc[i][j] = fmaf(a[i], b[j], acc[i][j]);
    }

    #pragma unroll
    for (int i = 0; i < 8; ++i) {
        float sc = ssum[t0 + i];
        size_t row = (size_t)tileIdx*128 + t0 + i;
        float4 o0, o1;
        o0.x = sc * __expf(acc[i][0]); o0.y = sc * __expf(acc[i][1]);
        o0.z = sc * __expf(acc[i][2]); o0.w = sc * __expf(acc[i][3]);
        o1.x = sc * __expf(acc[i][4]); o1.y = sc * __expf(acc[i][5]);
        o1.z = sc * __expf(acc[i][6]); o1.w = sc * __expf(acc[i][7]);
        reinterpret_cast<float4*>(dst + row*DD + m0)[0] = o0;
        reinterpret_cast<float4*>(dst + row*DD + m0)[1] = o1;
    }
}

// ============================================================================
// Kernel 2: per-chunk state  Sc[i][j] = sum_t phiK[t][i] * V[t][j],
//           nc[i] = sum_t phiK[t][i].   grid = 64 (b*16+c), 256 threads
// ============================================================================
__global__ void __launch_bounds__(256, 1)
chunk_state_kernel(const float* __restrict__ V) {
    extern __shared__ float sm[];
    float* Ks = sm;             // natural k-major: Ks[t*LD + i]
    float* Vs = sm + DD*LD;     // Vs[t*LD + j]

    const int tid = threadIdx.x;
    const int b = blockIdx.x / NCH, c = blockIdx.x % NCH;
    const float* Kg = g_phiK + ((size_t)b*SS + c*CC)*DD;
    const float* Vg = V      + ((size_t)b*SS + c*CC)*DD;

    #pragma unroll
    for (int it = 0; it < 16; ++it) {
        int i = tid + it*256;
        int t = i >> 5, d4 = i & 31;
        reinterpret_cast<float4*>(&Ks[t*LD])[d4] = reinterpret_cast<const float4*>(Kg)[t*32 + d4];
        reinterpret_cast<float4*>(&Vs[t*LD])[d4] = reinterpret_cast<const float4*>(Vg)[t*32 + d4];
    }
    __syncthreads();

    const int tx = tid & 15, ty = tid >> 4;
    const int i0 = ty*8, j0 = tx*8;
    float acc[8][8];
    #pragma unroll
    for (int i = 0; i < 8; ++i)
        #pragma unroll
        for (int j = 0; j < 8; ++j) acc[i][j] = 0.f;

    #pragma unroll 4
    for (int t = 0; t < 128; ++t) {
        float a[8], bb[8];
        FRAG_LOAD(a,  &Ks[t*LD + i0]);
        FRAG_LOAD(bb, &Vs[t*LD + j0]);
        #pragma unroll
        for (int i = 0; i < 8; ++i)
            #pragma unroll
            for (int j = 0; j < 8; ++j)
                acc[i][j] = fmaf(a[i], bb[j], acc[i][j]);
    }

    float* Sg = g_Sc + (size_t)(b*NCH + c)*DD*DD;
    #pragma unroll
    for (int i = 0; i < 8; ++i) {
        float4 o0 = make_float4(acc[i][0], acc[i][1], acc[i][2], acc[i][3]);
        float4 o1 = make_float4(acc[i][4], acc[i][5], acc[i][6], acc[i][7]);
        reinterpret_cast<float4*>(Sg + (size_t)(i0+i)*DD + j0)[0] = o0;
        reinterpret_cast<float4*>(Sg + (size_t)(i0+i)*DD + j0)[1] = o1;
    }

    if (tid < 128) {
        float s = 0.f;
        #pragma unroll 8
        for (int t = 0; t < 128; ++t) s += Ks[t*LD + tid];
        g_nc[(size_t)(b*NCH + c)*DD + tid] = s;
    }
}

// ============================================================================
// Kernel 3: exclusive prefix over chunks.  grid = 64 (b*16+slab), 256 threads
// ============================================================================
__global__ void prefix_kernel() {
    const int b = blockIdx.x >> 4, slab = blockIdx.x & 15;
    const size_t base = (size_t)b*NCH*DD*DD;
    const int e0 = slab*1024 + threadIdx.x;
    float acc[4] = {0.f, 0.f, 0.f, 0.f};
    for (int c = 0; c < NCH; ++c) {
        size_t off = base + (size_t)c*DD*DD;
        #pragma unroll
        for (int k = 0; k < 4; ++k) {
            g_Mp[off + e0 + k*256] = acc[k];
            acc[k] += g_Sc[off + e0 + k*256];
        }
    }
    if (slab == 0 && threadIdx.x < 128) {
        float an = 0.f;
        int i = threadIdx.x;
        for (int c = 0; c < NCH; ++c) {
            g_Np[(size_t)(b*NCH + c)*DD + i] = an;
            an += g_nc[(size_t)(b*NCH + c)*DD + i];
        }
    }
}

// ============================================================================
// Kernel 4: per-chunk output.
//   A = phiQ phiK^T (masked s<=t), rs[t] = rowsum(A) + phiQ[t].Nprev
//   out = (A@V + phiQ@Mprev) / (rs + sign(rs)*1e-6)
// grid = 64 (b*16+c), 256 threads
// ============================================================================
__global__ void __launch_bounds__(256, 1)
output_kernel(const float* __restrict__ V, float* __restrict__ out) {
    extern __shared__ float sm[];
    float* Qs = sm;              // phiQ transposed: Qs[d*LD + t]
    float* B1 = sm + DD*LD;      // phiK^T, then Mprev, then V
    float* As = sm + 2*DD*LD;    // A transposed: As[s*LD + t] (masked)
    float* rs = sm + 3*DD*LD;    // [128] denominators
    float* Np = rs + 128;        // [128]

    const int tid = threadIdx.x;
    const int b = blockIdx.x / NCH, c = blockIdx.x % NCH;
    const int tx = tid & 15, ty = tid >> 4;
    const int t0 = ty*8, j0 = tx*8;     // j0 doubles as s0 in phase A

    const float* Qg = g_phiQ + ((size_t)b*SS + c*CC)*DD;
    const float* Kg = g_phiK + ((size_t)b*SS + c*CC)*DD;

    // load phiQ^T and phiK^T
    #pragma unroll
    for (int it = 0; it < 16; ++it) {
        int i = tid + it*256;
        int t = i >> 5, d4 = i & 31;
        float4 q = reinterpret_cast<const float4*>(Qg)[t*32 + d4];
        Qs[(d4*4+0)*LD + t] = q.x; Qs[(d4*4+1)*LD + t] = q.y;
        Qs[(d4*4+2)*LD + t] = q.z; Qs[(d4*4+3)*LD + t] = q.w;
        float4 k = reinterpret_cast<const float4*>(Kg)[t*32 + d4];
        B1[(d4*4+0)*LD + t] = k.x; B1[(d4*4+1)*LD + t] = k.y;
        B1[(d4*4+2)*LD + t] = k.z; B1[(d4*4+3)*LD + t] = k.w;
    }
    if (tid < 128) Np[tid] = g_Np[(size_t)(b*NCH + c)*DD + tid];
    __syncthreads();

    // ---- Phase A: A[t][s] = sum_d phiQ[t][d]*phiK[s][d] ----
    {
        float acc[8][8];
        #pragma unroll
        for (int i = 0; i < 8; ++i)
            #pragma unroll
            for (int j = 0; j < 8; ++j) acc[i][j] = 0.f;
        #pragma unroll 4
        for (int d = 0; d < 128; ++d) {
            float a[8], bb[8];
            FRAG_LOAD(a,  &Qs[d*LD + t0]);
            FRAG_LOAD(bb, &B1[d*LD + j0]);
            #pragma unroll
            for (int i = 0; i < 8; ++i)
                #pragma unroll
                for (int j = 0; j < 8; ++j)
                    acc[i][j] = fmaf(a[i], bb[j], acc[i][j]);
        }
        // write masked, transposed: As[s][t]
        #pragma unroll
        for (int j = 0; j < 8; ++j) {
            int s = j0 + j;
            #pragma unroll
            for (int i = 0; i < 8; ++i) {
                int t = t0 + i;
                As[s*LD + t] = (s <= t) ? acc[i][j] : 0.f;
            }
        }
    }
    __syncthreads();

    // denominators
    if (tid < 128) {
        int t = tid;
        float r = 0.f;
        #pragma unroll 8
        for (int s = 0; s < 128; ++s) r += As[s*LD + t];
        float q = 0.f;
        #pragma unroll 8
        for (int d = 0; d < 128; ++d) q = fmaf(Qs[d*LD + t], Np[d], q);
        rs[t] = r + q;
    }
    __syncthreads();

    // ---- Phase B: C = phiQ @ Mprev ----
    const float* Mg = g_Mp + (size_t)(b*NCH + c)*DD*DD;
    #pragma unroll
    for (int it = 0; it < 16; ++it) {
        int i = tid + it*256;
        int d = i >> 5, j4 = i & 31;
        reinterpret_cast<float4*>(&B1[d*LD])[j4] = reinterpret_cast<const float4*>(Mg)[d*32 + j4];
    }
    __syncthreads();

    float cacc[8][8];
    #pragma unroll
    for (int i = 0; i < 8; ++i)
        #pragma unroll
        for (int j = 0; j < 8; ++j) cacc[i][j] = 0.f;

    #pragma unroll 4
    for (int d = 0; d < 128; ++d) {
        float a[8], bb[8];
        FRAG_LOAD(a,  &Qs[d*LD + t0]);
        FRAG_LOAD(bb, &B1[d*LD + j0]);
        #pragma unroll
        for (int i = 0; i < 8; ++i)
            #pragma unroll
            for (int j = 0; j < 8; ++j)
                cacc[i][j] = fmaf(a[i], bb[j], cacc[i][j]);
    }
    __syncthreads();

    // ---- Phase C: C += A_masked @ V ----
    const float* Vg = V + ((size_t)b*SS + c*CC)*DD;
    #pragma unroll
    for (int it = 0; it < 16; ++it) {
        int i = tid + it*256;
        int s = i >> 5, j4 = i & 31;
        reinterpret_cast<float4*>(&B1[s*LD])[j4] = reinterpret_cast<const float4*>(Vg)[s*32 + j4];
    }
    __syncthreads();

    #pragma unroll 4
    for (int s = 0; s < 128; ++s) {
        float a[8], bb[8];
        FRAG_LOAD(a,  &As[s*LD + t0]);
        FRAG_LOAD(bb, &B1[s*LD + j0]);
        #pragma unroll
        for (int i = 0; i < 8; ++i)
            #pragma unroll
            for (int j = 0; j < 8; ++j)
                cacc[i][j] = fmaf(a[i], bb[j], cacc[i][j]);
    }

    // write output with denominator
    #pragma unroll
    for (int i = 0; i < 8; ++i) {
        int t = t0 + i;
        float r = rs[t];
        float den = r + (r > 0.f ? 1e-6f : (r < 0.f ? -1e-6f : 0.f));
        float inv = 1.f / den;
        size_t row = (size_t)b*SS + (size_t)c*CC + t;
        float4 o0 = make_float4(cacc[i][0]*inv, cacc[i][1]*inv, cacc[i][2]*inv, cacc[i][3]*inv);
        float4 o1 = make_float4(cacc[i][4]*inv, cacc[i][5]*inv, cacc[i][6]*inv, cacc[i][7]*inv);
        reinterpret_cast<float4*>(out + row*DD + j0)[0] = o0;
        reinterpret_cast<float4*>(out + row*DD + j0)[1] = o1;
    }
}

// ============================================================================
extern "C" void kernel_launch(void* const* d_in, const int* in_sizes, int n_in,
                              void* d_out, int out_size) {
    const float* K = (const float*)d_in[0];
    const float* Q = (const float*)d_in[1];
    const float* V = (const float*)d_in[2];
    // d_in[3] = sent_embed_slice (unused), d_in[4] = max_seq_length,
    // d_in[5] = qkv_size, d_in[6] = W_phi
    const float* W = (const float*)d_in[6];
    float* out = (float*)d_out;

    const int SMEM1 = (2*DD*LD + 128) * 4;        // ~132 KB
    const int SMEM2 = (2*DD*LD) * 4;              // ~132 KB
    const int SMEM4 = (3*DD*LD + 256) * 4;        // ~199 KB

    cudaFuncSetAttribute(phi_kernel,         cudaFuncAttributeMaxDynamicSharedMemorySize, SMEM1);
    cudaFuncSetAttribute(chunk_state_kernel, cudaFuncAttributeMaxDynamicSharedMemorySize, SMEM2);
    cudaFuncSetAttribute(output_kernel,      cudaFuncAttributeMaxDynamicSharedMemorySize, SMEM4);

    phi_kernel<<<128, 256, SMEM1>>>(K, Q, W);
    chunk_state_kernel<<<64, 256, SMEM2>>>(V);
    prefix_kernel<<<64, 256>>>();
    output_kernel<<<64, 256, SMEM4>>>(V, out);
}

// round 3
// speedup vs baseline: 1.4400x; 1.4400x over previous
#include <cuda_runtime.h>
#include <cstdint>

#define BB 4
#define SS 2048
#define DD 128
#define CC 128
#define NCH 16
#define LD 132        // smem row stride in floats (mult of 4 -> 16B rows for ldmatrix)

// ------------------- scratch (device globals; no allocs allowed) -------------------
__device__ float g_phiK[BB*SS*DD];
__device__ float g_phiQ[BB*SS*DD];
__device__ float g_ScT [BB*NCH*DD*DD];   // transposed chunk state: ScT[e][d] = sum_t V[t][e] phiK[t][d]
__device__ float g_nc  [BB*NCH*DD];
__device__ float g_MpT [BB*NCH*DD*DD];   // exclusive prefix of g_ScT (still [e][d])
__device__ float g_Np  [BB*NCH*DD];

// ------------------- helpers -------------------
__device__ __forceinline__ float tf32r(float x){
    uint32_t r; asm("cvt.rna.tf32.f32 %0, %1;" : "=r"(r) : "f"(x));
    return __uint_as_float(r);
}
__device__ __forceinline__ float4 tf32r4(float4 v){
    v.x = tf32r(v.x); v.y = tf32r(v.y); v.z = tf32r(v.z); v.w = tf32r(v.w);
    return v;
}
__device__ __forceinline__ uint32_t sptr(const void* p){
    return (uint32_t)__cvta_generic_to_shared(p);
}

#define MMA8(d, a, b0v, b1v) \
    asm volatile("mma.sync.aligned.m16n8k8.row.col.f32.tf32.tf32.f32 " \
        "{%0,%1,%2,%3},{%4,%5,%6,%7},{%8,%9},{%0,%1,%2,%3};" \
        : "+f"(d[0]),"+f"(d[1]),"+f"(d[2]),"+f"(d[3]) \
        : "r"(a[0]),"r"(a[1]),"r"(a[2]),"r"(a[3]),"r"(b0v),"r"(b1v))

#define LDSMX4(r, addr) \
    asm volatile("ldmatrix.sync.aligned.m8n8.x4.shared.b16 {%0,%1,%2,%3},[%4];" \
        : "=r"(r[0]),"=r"(r[1]),"=r"(r[2]),"=r"(r[3]) : "r"(addr))

#define LDSMX2(r0, r1, addr) \
    asm volatile("ldmatrix.sync.aligned.m8n8.x2.shared.b16 {%0,%1},[%2];" \
        : "=r"(r0),"=r"(r1) : "r"(addr))

// per-lane fragment address offsets (A: m16k8 via x4, B: n8k8 via x2; both k-minor in smem)
#define FRAG_OFFS() \
    const int rowA = (lane & 7) + ((lane >> 3) & 1) * 8; \
    const int colA = (lane >> 4) * 4;                    \
    const int rowB = lane & 7;                           \
    const int colB = ((lane >> 3) & 1) * 4;              \
    const int er   = lane >> 2;                          \
    const int ec   = (lane & 3) * 2;

// ============================================================================
// Kernel 1: phi(X) = exp(-0.5*||x||)/sqrt(128) * exp(X @ W^T)
// grid = 128 (64 row-tiles x {K,Q}), 256 threads
// ============================================================================
__global__ void __launch_bounds__(256, 1)
phi_kernel(const float* __restrict__ K, const float* __restrict__ Q,
           const float* __restrict__ W) {
    extern __shared__ float sm[];
    float* Xs    = sm;             // [128][LD] row-major t x d (tf32-rounded)
    float* Ws    = sm + DD*LD;     // [128][LD] row-major m x d (tf32-rounded)
    float* scale = sm + 2*DD*LD;   // [128]

    const int tid  = threadIdx.x;
    const int lane = tid & 31;
    const int wid  = tid >> 5;
    const int tileIdx = blockIdx.x & 63;
    const int sel     = blockIdx.x >> 6;
    const float* src  = sel ? Q : K;
    float*       dst  = sel ? g_phiQ : g_phiK;
    const float* Xg   = src + (size_t)tileIdx * 128 * DD;

    if (tid < 128) scale[tid] = 0.f;
    __syncthreads();

    #pragma unroll
    for (int it = 0; it < 16; ++it) {
        int i = tid + it*256;
        int t = i >> 5, d4 = i & 31;
        float4 v = reinterpret_cast<const float4*>(Xg)[t*32 + d4];
        float ls = v.x*v.x + v.y*v.y + v.z*v.z + v.w*v.w;
        ls += __shfl_xor_sync(~0u, ls, 16);
        ls += __shfl_xor_sync(~0u, ls, 8);
        ls += __shfl_xor_sync(~0u, ls, 4);
        ls += __shfl_xor_sync(~0u, ls, 2);
        ls += __shfl_xor_sync(~0u, ls, 1);
        if (lane == 0) atomicAdd(&scale[t], ls);
        reinterpret_cast<float4*>(Xs + t*LD)[d4] = tf32r4(v);
        float4 w = reinterpret_cast<const float4*>(W)[t*32 + d4];
        reinterpret_cast<float4*>(Ws + t*LD)[d4] = tf32r4(w);
    }
    __syncthreads();
    if (tid < 128)
        scale[tid] = __expf(-0.5f * sqrtf(scale[tid])) * 0.08838834764831845f;
    __syncthreads();

    const int wm0 = (wid >> 1) * 32;
    const int wn0 = (wid & 1) * 64;
    FRAG_OFFS();
    const uint32_t uX = sptr(Xs), uW = sptr(Ws);

    float acc[2][8][4];
    #pragma unroll
    for (int mi = 0; mi < 2; ++mi)
        #pragma unroll
        for (int ni = 0; ni < 8; ++ni)
            #pragma unroll
            for (int q = 0; q < 4; ++q) acc[mi][ni][q] = 0.f;

    #pragma unroll
    for (int k0 = 0; k0 < 128; k0 += 8) {
        uint32_t a[2][4];
        #pragma unroll
        for (int mi = 0; mi < 2; ++mi)
            LDSMX4(a[mi], uX + (uint32_t)(((wm0 + mi*16 + rowA)*LD + k0 + colA) << 2));
        uint32_t b[8][2];
        #pragma unroll
        for (int ni = 0; ni < 8; ++ni)
            LDSMX2(b[ni][0], b[ni][1], uW + (uint32_t)(((wn0 + ni*8 + rowB)*LD + k0 + colB) << 2));
        #pragma unroll
        for (int mi = 0; mi < 2; ++mi)
            #pragma unroll
            for (int ni = 0; ni < 8; ++ni)
                MMA8(acc[mi][ni], a[mi], b[ni][0], b[ni][1]);
    }

    #pragma unroll
    for (int mi = 0; mi < 2; ++mi) {
        int r0 = wm0 + mi*16 + er;
        float s0 = scale[r0], s1 = scale[r0 + 8];
        size_t g0 = ((size_t)tileIdx*128 + r0) * DD;
        #pragma unroll
        for (int ni = 0; ni < 8; ++ni) {
            int col = wn0 + ni*8 + ec;
            float2 o0 = make_float2(s0*__expf(acc[mi][ni][0]), s0*__expf(acc[mi][ni][1]));
            float2 o1 = make_float2(s1*__expf(acc[mi][ni][2]), s1*__expf(acc[mi][ni][3]));
            *reinterpret_cast<float2*>(dst + g0 + col)        = o0;
            *reinterpret_cast<float2*>(dst + g0 + 8*DD + col) = o1;
        }
    }
}

// ============================================================================
// Kernel 2: transposed chunk state  ScT[e][d] = sum_t V[t][e]*phiK[t][d]
// grid = 128 (64 chunks x 2 e-halves), 256 threads
// ============================================================================
__global__ void __launch_bounds__(256, 1)
chunk_state_kernel(const float* __restrict__ V) {
    extern __shared__ float sm[];
    float* Vt = sm;              // [64][LD]  V^T half (rows e-local, cols t)
    float* Kt = sm + 64*LD;      // [128][LD] phiK^T (rows d, cols t)

    const int tid = threadIdx.x, lane = tid & 31, wid = tid >> 5;
    const int chunk = blockIdx.x >> 1, h = blockIdx.x & 1;
    const int b = chunk / NCH, ch = chunk % NCH;
    const float* Kg = g_phiK + ((size_t)b*SS + ch*CC)*DD;
    const float* Vg = V      + ((size_t)b*SS + ch*CC)*DD;

    // transposed loads, lane == t (bank-conflict-free scalar STS)
    #pragma unroll
    for (int it = 0; it < 16; ++it) {
        int i = tid + it*256;
        int d4 = i >> 7, t = i & 127;
        float4 k = tf32r4(reinterpret_cast<const float4*>(Kg)[t*32 + d4]);
        Kt[(d4*4+0)*LD + t] = k.x;
        Kt[(d4*4+1)*LD + t] = k.y;
        Kt[(d4*4+2)*LD + t] = k.z;
        Kt[(d4*4+3)*LD + t] = k.w;
    }
    #pragma unroll
    for (int it = 0; it < 8; ++it) {
        int i = tid + it*256;
        int d4h = i >> 7, t = i & 127;
        float4 v = tf32r4(reinterpret_cast<const float4*>(Vg)[t*32 + h*16 + d4h]);
        Vt[(d4h*4+0)*LD + t] = v.x;
        Vt[(d4h*4+1)*LD + t] = v.y;
        Vt[(d4h*4+2)*LD + t] = v.z;
        Vt[(d4h*4+3)*LD + t] = v.w;
    }
    __syncthreads();

    const int wm0 = (wid >> 1) * 16;   // 64 rows / 4
    const int wn0 = (wid & 1) * 64;
    FRAG_OFFS();
    const uint32_t uV = sptr(Vt), uK = sptr(Kt);

    float acc[8][4];
    #pragma unroll
    for (int ni = 0; ni < 8; ++ni)
        #pragma unroll
        for (int q = 0; q < 4; ++q) acc[ni][q] = 0.f;

    #pragma unroll
    for (int k0 = 0; k0 < 128; k0 += 8) {
        uint32_t a[4];
        LDSMX4(a, uV + (uint32_t)(((wm0 + rowA)*LD + k0 + colA) << 2));
        uint32_t b[8][2];
        #pragma unroll
        for (int ni = 0; ni < 8; ++ni)
            LDSMX2(b[ni][0], b[ni][1], uK + (uint32_t)(((wn0 + ni*8 + rowB)*LD + k0 + colB) << 2));
        #pragma unroll
        for (int ni = 0; ni < 8; ++ni)
            MMA8(acc[ni], a, b[ni][0], b[ni][1]);
    }

    float* Sg = g_ScT + (size_t)(b*NCH + ch)*DD*DD;
    {
        int r0 = h*64 + wm0 + er;
        #pragma unroll
        for (int ni = 0; ni < 8; ++ni) {
            int col = wn0 + ni*8 + ec;
            *reinterpret_cast<float2*>(Sg + (size_t)r0*DD + col)     = make_float2(acc[ni][0], acc[ni][1]);
            *reinterpret_cast<float2*>(Sg + (size_t)(r0+8)*DD + col) = make_float2(acc[ni][2], acc[ni][3]);
        }
    }

    if (h == 0 && tid < 128) {
        float s = 0.f;
        #pragma unroll 8
        for (int t = 0; t < 128; ++t) s += Kt[tid*LD + t];
        g_nc[(size_t)(b*NCH + ch)*DD + tid] = s;
    }
}

// ============================================================================
// Kernel 3: exclusive prefix over chunks (elementwise on ScT).  grid=64
// ============================================================================
__global__ void prefix_kernel() {
    const int b = blockIdx.x >> 4, slab = blockIdx.x & 15;
    const size_t base = (size_t)b*NCH*DD*DD;
    const int e0 = slab*1024 + threadIdx.x;
    float acc[4] = {0.f, 0.f, 0.f, 0.f};
    for (int c = 0; c < NCH; ++c) {
        size_t off = base + (size_t)c*DD*DD;
        #pragma unroll
        for (int k = 0; k < 4; ++k) {
            g_MpT[off + e0 + k*256] = acc[k];
            acc[k] += g_ScT[off + e0 + k*256];
        }
    }
    if (slab == 0 && threadIdx.x < 128) {
        float an = 0.f;
        int i = threadIdx.x;
        for (int c = 0; c < NCH; ++c) {
            g_Np[(size_t)(b*NCH + c)*DD + i] = an;
            an += g_nc[(size_t)(b*NCH + c)*DD + i];
        }
    }
}

// ============================================================================
// Kernel 4: per-chunk output, split on output columns.
// grid = 128 (64 chunks x 2 j-halves), 256 threads
// ============================================================================
__global__ void __launch_bounds__(256, 1)
output_kernel(const float* __restrict__ V, float* __restrict__ out) {
    extern __shared__ float sm[];
    float* Qs = sm;              // [128][LD] phiQ row-major (tf32)
    float* Bs = sm + DD*LD;      // [128][LD] phiK, later Mp-half(rows 0-63) + V^T-half(rows 64-127)
    float* As = sm + 2*DD*LD;    // [128][LD] masked A row-major t x s (tf32)
    float* rs = sm + 3*DD*LD;    // [128]
    float* Np = rs + 128;        // [128]

    const int tid = threadIdx.x, lane = tid & 31, wid = tid >> 5;
    const int chunk = blockIdx.x >> 1, h = blockIdx.x & 1;
    const int b = chunk / NCH, ch = chunk % NCH;
    const int j0h = h * 64;

    const float* Qg = g_phiQ + ((size_t)b*SS + ch*CC)*DD;
    const float* Kg = g_phiK + ((size_t)b*SS + ch*CC)*DD;

    if (tid < 128) {
        rs[tid] = 0.f;
        Np[tid] = g_Np[(size_t)(b*NCH + ch)*DD + tid];
    }
    #pragma unroll
    for (int it = 0; it < 16; ++it) {
        int i = tid + it*256;
        int t = i >> 5, d4 = i & 31;
        reinterpret_cast<float4*>(Qs + t*LD)[d4] = tf32r4(reinterpret_cast<const float4*>(Qg)[t*32 + d4]);
        reinterpret_cast<float4*>(Bs + t*LD)[d4] = tf32r4(reinterpret_cast<const float4*>(Kg)[t*32 + d4]);
    }
    __syncthreads();

    const int wm0 = (wid >> 1) * 32;
    FRAG_OFFS();
    const uint32_t uQ = sptr(Qs), uB = sptr(Bs), uA = sptr(As);

    // ---- Phase A: A[t][s] = phiQ . phiK (full 128x128), masked store ----
    {
        const int wn0 = (wid & 1) * 64;
        float acc[2][8][4];
        #pragma unroll
        for (int mi = 0; mi < 2; ++mi)
            #pragma unroll
            for (int ni = 0; ni < 8; ++ni)
                #pragma unroll
                for (int q = 0; q < 4; ++q) acc[mi][ni][q] = 0.f;

        #pragma unroll
        for (int k0 = 0; k0 < 128; k0 += 8) {
            uint32_t a[2][4];
            #pragma unroll
            for (int mi = 0; mi < 2; ++mi)
                LDSMX4(a[mi], uQ + (uint32_t)(((wm0 + mi*16 + rowA)*LD + k0 + colA) << 2));
            uint32_t bf[8][2];
            #pragma unroll
            for (int ni = 0; ni < 8; ++ni)
                LDSMX2(bf[ni][0], bf[ni][1], uB + (uint32_t)(((wn0 + ni*8 + rowB)*LD + k0 + colB) << 2));
            #pragma unroll
            for (int mi = 0; mi < 2; ++mi)
                #pragma unroll
                for (int ni = 0; ni < 8; ++ni)
                    MMA8(acc[mi][ni], a[mi], bf[ni][0], bf[ni][1]);
        }

        #pragma unroll
        for (int mi = 0; mi < 2; ++mi) {
            int t0 = wm0 + mi*16 + er;
            int t1 = t0 + 8;
            #pragma unroll
            for (int ni = 0; ni < 8; ++ni) {
                int s0 = wn0 + ni*8 + ec;
                float v0 = (s0     <= t0) ? tf32r(acc[mi][ni][0]) : 0.f;
                float v1 = (s0 + 1 <= t0) ? tf32r(acc[mi][ni][1]) : 0.f;
                float v2 = (s0     <= t1) ? tf32r(acc[mi][ni][2]) : 0.f;
                float v3 = (s0 + 1 <= t1) ? tf32r(acc[mi][ni][3]) : 0.f;
                *reinterpret_cast<float2*>(As + t0*LD + s0) = make_float2(v0, v1);
                *reinterpret_cast<float2*>(As + t1*LD + s0) = make_float2(v2, v3);
            }
        }
    }
    __syncthreads();

    // ---- denominators (split across 2 thread groups) + reload Bs ----
    {
        int t = tid & 127, p = tid >> 7;
        float r = 0.f;
        const int s0 = p * 64;
        #pragma unroll 8
        for (int s = s0; s < s0 + 64; ++s) r += As[t*LD + s];
        #pragma unroll 8
        for (int d = s0; d < s0 + 64; ++d) r = fmaf(Qs[t*LD + d], Np[d], r);
        atomicAdd(&rs[t], r);
    }
    const float* Mg = g_MpT + (size_t)(b*NCH + ch)*DD*DD;
    #pragma unroll
    for (int it = 0; it < 8; ++it) {
        int i = tid + it*256;
        int e = i >> 5, d4 = i & 31;
        reinterpret_cast<float4*>(Bs + e*LD)[d4] =
            tf32r4(reinterpret_cast<const float4*>(Mg)[(j0h + e)*32 + d4]);
    }
    const float* Vg = V + ((size_t)b*SS + ch*CC)*DD;
    #pragma unroll
    for (int it = 0; it < 8; ++it) {
        int i = tid + it*256;
        int d4h = i >> 7, t = i & 127;
        float4 v = tf32r4(reinterpret_cast<const float4*>(Vg)[t*32 + h*16 + d4h]);
        Bs[(64 + d4h*4+0)*LD + t] = v.x;
        Bs[(64 + d4h*4+1)*LD + t] = v.y;
        Bs[(64 + d4h*4+2)*LD + t] = v.z;
        Bs[(64 + d4h*4+3)*LD + t] = v.w;
    }
    __syncthreads();

    // ---- Phase B+C: C = phiQ @ Mprev_half + A_masked @ V_half  (128 x 64) ----
    {
        const int wn0 = (wid & 1) * 32;
        float acc[2][4][4];
        #pragma unroll
        for (int mi = 0; mi < 2; ++mi)
            #pragma unroll
            for (int ni = 0; ni < 4; ++ni)
                #pragma unroll
                for (int q = 0; q < 4; ++q) acc[mi][ni][q] = 0.f;

        #pragma unroll
        for (int k0 = 0; k0 < 128; k0 += 8) {      // phiQ @ MpT^T  (B rows 0-63)
            uint32_t a[2][4];
            #pragma unroll
            for (int mi = 0; mi < 2; ++mi)
                LDSMX4(a[mi], uQ + (uint32_t)(((wm0 + mi*16 + rowA)*LD + k0 + colA) << 2));
            uint32_t bf[4][2];
            #pragma unroll
            for (int ni = 0; ni < 4; ++ni)
                LDSMX2(bf[ni][0], bf[ni][1], uB + (uint32_t)(((wn0 + ni*8 + rowB)*LD + k0 + colB) << 2));
            #pragma unroll
            for (int mi = 0; mi < 2; ++mi)
                #pragma unroll
                for (int ni = 0; ni < 4; ++ni)
                    MMA8(acc[mi][ni], a[mi], bf[ni][0], bf[ni][1]);
        }
        #pragma unroll
        for (int k0 = 0; k0 < 128; k0 += 8) {      // A_masked @ V^T  (B rows 64-127)
            uint32_t a[2][4];
            #pragma unroll
            for (int mi = 0; mi < 2; ++mi)
                LDSMX4(a[mi], uA + (uint32_t)(((wm0 + mi*16 + rowA)*LD + k0 + colA) << 2));
            uint32_t bf[4][2];
            #pragma unroll
            for (int ni = 0; ni < 4; ++ni)
                LDSMX2(bf[ni][0], bf[ni][1], uB + (uint32_t)(((64 + wn0 + ni*8 + rowB)*LD + k0 + colB) << 2));
            #pragma unroll
            for (int mi = 0; mi < 2; ++mi)
                #pragma unroll
                for (int ni = 0; ni < 4; ++ni)
                    MMA8(acc[mi][ni], a[mi], bf[ni][0], bf[ni][1]);
        }

        #pragma unroll
        for (int mi = 0; mi < 2; ++mi) {
            int t0 = wm0 + mi*16 + er;
            float r0 = rs[t0];
            float inv0 = 1.f / (r0 + (r0 > 0.f ? 1e-6f : (r0 < 0.f ? -1e-6f : 0.f)));
            float r1 = rs[t0 + 8];
            float inv1 = 1.f / (r1 + (r1 > 0.f ? 1e-6f : (r1 < 0.f ? -1e-6f : 0.f)));
            size_t row0 = (size_t)b*SS + (size_t)ch*CC + t0;
            #pragma unroll
            for (int ni = 0; ni < 4; ++ni) {
                int col = j0h + wn0 + ni*8 + ec;
                *reinterpret_cast<float2*>(out + row0*DD + col) =
                    make_float2(acc[mi][ni][0]*inv0, acc[mi][ni][1]*inv0);
                *reinterpret_cast<float2*>(out + (row0 + 8)*DD + col) =
                    make_float2(acc[mi][ni][2]*inv1, acc[mi][ni][3]*inv1);
            }
        }
    }
}

// ============================================================================
extern "C" void kernel_launch(void* const* d_in, const int* in_sizes, int n_in,
                              void* d_out, int out_size) {
    const float* K = (const float*)d_in[0];
    const float* Q = (const float*)d_in[1];
    const float* V = (const float*)d_in[2];
    const float* W = (const float*)d_in[6];
    float* out = (float*)d_out;

    const int SMEM1 = (2*DD*LD + 128) * 4;      // ~136 KB
    const int SMEM2 = (192*LD) * 4;             // ~101 KB
    const int SMEM4 = (3*DD*LD + 256) * 4;      // ~204 KB

    cudaFuncSetAttribute(phi_kernel,         cudaFuncAttributeMaxDynamicSharedMemorySize, SMEM1);
    cudaFuncSetAttribute(chunk_state_kernel, cudaFuncAttributeMaxDynamicSharedMemorySize, SMEM2);
    cudaFuncSetAttribute(output_kernel,      cudaFuncAttributeMaxDynamicSharedMemorySize, SMEM4);

    phi_kernel<<<128, 256, SMEM1>>>(K, Q, W);
    chunk_state_kernel<<<128, 256, SMEM2>>>(V);
    prefix_kernel<<<64, 256>>>();
    output_kernel<<<128, 256, SMEM4>>>(V, out);
}

// round 4
// speedup vs baseline: 2.3388x; 1.6242x over previous
#include <cuda_runtime.h>
#include <cstdint>

#define BB 4
#define SS 2048
#define DD 128
#define CC 128
#define NCH 16
#define LD 132        // smem row stride in floats (mult of 4 -> 16B rows for ldmatrix)

// ------------------- scratch (device globals; no allocs allowed) -------------------
__device__ float g_phiK[BB*SS*DD];
__device__ float g_phiQ[BB*SS*DD];
__device__ float g_ScT [BB*NCH*DD*DD];   // transposed chunk state: ScT[e][d] = sum_t V[t][e] phiK[t][d]
__device__ float g_nc  [BB*NCH*DD];
__device__ float g_MpT [BB*NCH*DD*DD];   // exclusive prefix of g_ScT (still [e][d])
__device__ float g_Np  [BB*NCH*DD];

// ------------------- helpers -------------------
__device__ __forceinline__ float tf32r(float x){
    uint32_t r; asm("cvt.rna.tf32.f32 %0, %1;" : "=r"(r) : "f"(x));
    return __uint_as_float(r);
}
__device__ __forceinline__ float4 tf32r4(float4 v){
    v.x = tf32r(v.x); v.y = tf32r(v.y); v.z = tf32r(v.z); v.w = tf32r(v.w);
    return v;
}
__device__ __forceinline__ uint32_t sptr(const void* p){
    return (uint32_t)__cvta_generic_to_shared(p);
}

#define MMA8(d, a, b0v, b1v) \
    asm volatile("mma.sync.aligned.m16n8k8.row.col.f32.tf32.tf32.f32 " \
        "{%0,%1,%2,%3},{%4,%5,%6,%7},{%8,%9},{%0,%1,%2,%3};" \
        : "+f"(d[0]),"+f"(d[1]),"+f"(d[2]),"+f"(d[3]) \
        : "r"(a[0]),"r"(a[1]),"r"(a[2]),"r"(a[3]),"r"(b0v),"r"(b1v))

#define LDSMX4(r, addr) \
    asm volatile("ldmatrix.sync.aligned.m8n8.x4.shared.b16 {%0,%1,%2,%3},[%4];" \
        : "=r"(r[0]),"=r"(r[1]),"=r"(r[2]),"=r"(r[3]) : "r"(addr))

#define LDSMX2(r0, r1, addr) \
    asm volatile("ldmatrix.sync.aligned.m8n8.x2.shared.b16 {%0,%1},[%2];" \
        : "=r"(r0),"=r"(r1) : "r"(addr))

// per-lane fragment address offsets (A: m16k8 via x4, B: n8k8 via x2; both k-minor in smem)
#define FRAG_OFFS() \
    const int rowA = (lane & 7) + ((lane >> 3) & 1) * 8; \
    const int colA = (lane >> 4) * 4;                    \
    const int rowB = lane & 7;                           \
    const int colB = ((lane >> 3) & 1) * 4;              \
    const int er   = lane >> 2;                          \
    const int ec   = (lane & 3) * 2;

// ============================================================================
// Kernel 1: phi(X) = exp(-0.5*||x||)/sqrt(128) * exp(X @ W^T)
// grid = 128 (64 row-tiles x {K,Q}), 512 threads, warp tile 32x32
// ============================================================================
__global__ void __launch_bounds__(512, 1)
phi_kernel(const float* __restrict__ K, const float* __restrict__ Q,
           const float* __restrict__ W) {
    extern __shared__ float sm[];
    float* Xs    = sm;             // [128][LD] row-major t x d (tf32-rounded)
    float* Ws    = sm + DD*LD;     // [128][LD] row-major m x d (tf32-rounded)
    float* scale = sm + 2*DD*LD;   // [128]

    const int tid  = threadIdx.x;
    const int lane = tid & 31;
    const int wid  = tid >> 5;
    const int tileIdx = blockIdx.x & 63;
    const int sel     = blockIdx.x >> 6;
    const float* src  = sel ? Q : K;
    float*       dst  = sel ? g_phiQ : g_phiK;
    const float* Xg   = src + (size_t)tileIdx * 128 * DD;

    if (tid < 128) scale[tid] = 0.f;
    __syncthreads();

    #pragma unroll
    for (int it = 0; it < 8; ++it) {
        int i = tid + it*512;
        int t = i >> 5, d4 = i & 31;
        float4 v = reinterpret_cast<const float4*>(Xg)[t*32 + d4];
        float ls = v.x*v.x + v.y*v.y + v.z*v.z + v.w*v.w;
        ls += __shfl_xor_sync(~0u, ls, 16);
        ls += __shfl_xor_sync(~0u, ls, 8);
        ls += __shfl_xor_sync(~0u, ls, 4);
        ls += __shfl_xor_sync(~0u, ls, 2);
        ls += __shfl_xor_sync(~0u, ls, 1);
        if (lane == 0) atomicAdd(&scale[t], ls);
        reinterpret_cast<float4*>(Xs + t*LD)[d4] = tf32r4(v);
        float4 w = reinterpret_cast<const float4*>(W)[t*32 + d4];
        reinterpret_cast<float4*>(Ws + t*LD)[d4] = tf32r4(w);
    }
    __syncthreads();
    if (tid < 128)
        scale[tid] = __expf(-0.5f * sqrtf(scale[tid])) * 0.08838834764831845f;
    __syncthreads();

    const int wm0 = (wid >> 2) * 32;
    const int wn0 = (wid & 3) * 32;
    FRAG_OFFS();
    const uint32_t uX = sptr(Xs), uW = sptr(Ws);

    float acc[2][4][4];
    #pragma unroll
    for (int mi = 0; mi < 2; ++mi)
        #pragma unroll
        for (int ni = 0; ni < 4; ++ni)
            #pragma unroll
            for (int q = 0; q < 4; ++q) acc[mi][ni][q] = 0.f;

    #pragma unroll
    for (int k0 = 0; k0 < 128; k0 += 8) {
        uint32_t a[2][4];
        #pragma unroll
        for (int mi = 0; mi < 2; ++mi)
            LDSMX4(a[mi], uX + (uint32_t)(((wm0 + mi*16 + rowA)*LD + k0 + colA) << 2));
        uint32_t b[4][2];
        #pragma unroll
        for (int ni = 0; ni < 4; ++ni)
            LDSMX2(b[ni][0], b[ni][1], uW + (uint32_t)(((wn0 + ni*8 + rowB)*LD + k0 + colB) << 2));
        #pragma unroll
        for (int mi = 0; mi < 2; ++mi)
            #pragma unroll
            for (int ni = 0; ni < 4; ++ni)
                MMA8(acc[mi][ni], a[mi], b[ni][0], b[ni][1]);
    }

    #pragma unroll
    for (int mi = 0; mi < 2; ++mi) {
        int r0 = wm0 + mi*16 + er;
        float s0 = scale[r0], s1 = scale[r0 + 8];
        size_t g0 = ((size_t)tileIdx*128 + r0) * DD;
        #pragma unroll
        for (int ni = 0; ni < 4; ++ni) {
            int col = wn0 + ni*8 + ec;
            float2 o0 = make_float2(s0*__expf(acc[mi][ni][0]), s0*__expf(acc[mi][ni][1]));
            float2 o1 = make_float2(s1*__expf(acc[mi][ni][2]), s1*__expf(acc[mi][ni][3]));
            *reinterpret_cast<float2*>(dst + g0 + col)        = o0;
            *reinterpret_cast<float2*>(dst + g0 + 8*DD + col) = o1;
        }
    }
}

// ============================================================================
// Kernel 2: transposed chunk state  ScT[e][d] = sum_t V[t][e]*phiK[t][d]
// grid = 64 chunks, 512 threads, warp tile 32x32
// ============================================================================
__global__ void __launch_bounds__(512, 1)
chunk_state_kernel(const float* __restrict__ V) {
    extern __shared__ float sm[];
    float* Vt = sm;              // [128][LD]  V^T (rows e, cols t)
    float* Kt = sm + DD*LD;      // [128][LD]  phiK^T (rows d, cols t)

    const int tid = threadIdx.x, lane = tid & 31, wid = tid >> 5;
    const int b = blockIdx.x / NCH, ch = blockIdx.x % NCH;
    const float* Kg = g_phiK + ((size_t)b*SS + ch*CC)*DD;
    const float* Vg = V      + ((size_t)b*SS + ch*CC)*DD;

    // transposed loads, lanes map to consecutive t (bank-conflict-free scalar STS)
    #pragma unroll
    for (int it = 0; it < 8; ++it) {
        int i = tid + it*512;
        int d4 = i >> 7, t = i & 127;
        float4 k = tf32r4(reinterpret_cast<const float4*>(Kg)[t*32 + d4]);
        Kt[(d4*4+0)*LD + t] = k.x;
        Kt[(d4*4+1)*LD + t] = k.y;
        Kt[(d4*4+2)*LD + t] = k.z;
        Kt[(d4*4+3)*LD + t] = k.w;
        float4 v = tf32r4(reinterpret_cast<const float4*>(Vg)[t*32 + d4]);
        Vt[(d4*4+0)*LD + t] = v.x;
        Vt[(d4*4+1)*LD + t] = v.y;
        Vt[(d4*4+2)*LD + t] = v.z;
        Vt[(d4*4+3)*LD + t] = v.w;
    }
    __syncthreads();

    const int wm0 = (wid >> 2) * 32;
    const int wn0 = (wid & 3) * 32;
    FRAG_OFFS();
    const uint32_t uV = sptr(Vt), uK = sptr(Kt);

    float acc[2][4][4];
    #pragma unroll
    for (int mi = 0; mi < 2; ++mi)
        #pragma unroll
        for (int ni = 0; ni < 4; ++ni)
            #pragma unroll
            for (int q = 0; q < 4; ++q) acc[mi][ni][q] = 0.f;

    #pragma unroll
    for (int k0 = 0; k0 < 128; k0 += 8) {
        uint32_t a[2][4];
        #pragma unroll
        for (int mi = 0; mi < 2; ++mi)
            LDSMX4(a[mi], uV + (uint32_t)(((wm0 + mi*16 + rowA)*LD + k0 + colA) << 2));
        uint32_t b[4][2];
        #pragma unroll
        for (int ni = 0; ni < 4; ++ni)
            LDSMX2(b[ni][0], b[ni][1], uK + (uint32_t)(((wn0 + ni*8 + rowB)*LD + k0 + colB) << 2));
        #pragma unroll
        for (int mi = 0; mi < 2; ++mi)
            #pragma unroll
            for (int ni = 0; ni < 4; ++ni)
                MMA8(acc[mi][ni], a[mi], b[ni][0], b[ni][1]);
    }

    float* Sg = g_ScT + (size_t)(b*NCH + ch)*DD*DD;
    #pragma unroll
    for (int mi = 0; mi < 2; ++mi) {
        int r0 = wm0 + mi*16 + er;
        #pragma unroll
        for (int ni = 0; ni < 4; ++ni) {
            int col = wn0 + ni*8 + ec;
            *reinterpret_cast<float2*>(Sg + (size_t)r0*DD + col)     = make_float2(acc[mi][ni][0], acc[mi][ni][1]);
            *reinterpret_cast<float2*>(Sg + (size_t)(r0+8)*DD + col) = make_float2(acc[mi][ni][2], acc[mi][ni][3]);
        }
    }

    if (tid < 128) {
        float s = 0.f;
        #pragma unroll 8
        for (int t = 0; t < 128; ++t) s += Kt[tid*LD + t];
        g_nc[(size_t)(b*NCH + ch)*DD + tid] = s;
    }
}

// ============================================================================
// Kernel 3: exclusive prefix over chunks (elementwise on ScT).  grid=64
// ============================================================================
__global__ void prefix_kernel() {
    const int b = blockIdx.x >> 4, slab = blockIdx.x & 15;
    const size_t base = (size_t)b*NCH*DD*DD;
    const int e0 = slab*1024 + threadIdx.x;
    float acc[4] = {0.f, 0.f, 0.f, 0.f};
    for (int c = 0; c < NCH; ++c) {
        size_t off = base + (size_t)c*DD*DD;
        #pragma unroll
        for (int k = 0; k < 4; ++k) {
            g_MpT[off + e0 + k*256] = acc[k];
            acc[k] += g_ScT[off + e0 + k*256];
        }
    }
    if (slab == 0 && threadIdx.x < 128) {
        float an = 0.f;
        int i = threadIdx.x;
        for (int c = 0; c < NCH; ++c) {
            g_Np[(size_t)(b*NCH + c)*DD + i] = an;
            an += g_nc[(size_t)(b*NCH + c)*DD + i];
        }
    }
}

// ============================================================================
// Kernel 4: per-chunk output, split on output columns.
// grid = 128 (64 chunks x 2 j-halves), 512 threads
// ============================================================================
__global__ void __launch_bounds__(512, 1)
output_kernel(const float* __restrict__ V, float* __restrict__ out) {
    extern __shared__ float sm[];
    float* Qs = sm;              // [128][LD] phiQ row-major (tf32)
    float* Bs = sm + DD*LD;      // [128][LD] phiK, later Mp-half(rows 0-63) + V^T-half(rows 64-127)
    float* As = sm + 2*DD*LD;    // [128][LD] masked A row-major t x s (tf32)
    float* rs = sm + 3*DD*LD;    // [128]
    float* Np = rs + 128;        // [128]

    const int tid = threadIdx.x, lane = tid & 31, wid = tid >> 5;
    const int chunk = blockIdx.x >> 1, h = blockIdx.x & 1;
    const int b = chunk / NCH, ch = chunk % NCH;
    const int j0h = h * 64;

    const float* Qg = g_phiQ + ((size_t)b*SS + ch*CC)*DD;
    const float* Kg = g_phiK + ((size_t)b*SS + ch*CC)*DD;

    if (tid < 128) {
        rs[tid] = 0.f;
        Np[tid] = g_Np[(size_t)(b*NCH + ch)*DD + tid];
    }
    #pragma unroll
    for (int it = 0; it < 8; ++it) {
        int i = tid + it*512;
        int t = i >> 5, d4 = i & 31;
        reinterpret_cast<float4*>(Qs + t*LD)[d4] = tf32r4(reinterpret_cast<const float4*>(Qg)[t*32 + d4]);
        reinterpret_cast<float4*>(Bs + t*LD)[d4] = tf32r4(reinterpret_cast<const float4*>(Kg)[t*32 + d4]);
    }
    __syncthreads();

    const int wm0 = (wid >> 2) * 32;
    FRAG_OFFS();
    const uint32_t uQ = sptr(Qs), uB = sptr(Bs), uA = sptr(As);

    // ---- Phase A: A[t][s] = phiQ . phiK (full 128x128), masked store ----
    {
        const int wn0 = (wid & 3) * 32;
        float acc[2][4][4];
        #pragma unroll
        for (int mi = 0; mi < 2; ++mi)
            #pragma unroll
            for (int ni = 0; ni < 4; ++ni)
                #pragma unroll
                for (int q = 0; q < 4; ++q) acc[mi][ni][q] = 0.f;

        #pragma unroll
        for (int k0 = 0; k0 < 128; k0 += 8) {
            uint32_t a[2][4];
            #pragma unroll
            for (int mi = 0; mi < 2; ++mi)
                LDSMX4(a[mi], uQ + (uint32_t)(((wm0 + mi*16 + rowA)*LD + k0 + colA) << 2));
            uint32_t bf[4][2];
            #pragma unroll
            for (int ni = 0; ni < 4; ++ni)
                LDSMX2(bf[ni][0], bf[ni][1], uB + (uint32_t)(((wn0 + ni*8 + rowB)*LD + k0 + colB) << 2));
            #pragma unroll
            for (int mi = 0; mi < 2; ++mi)
                #pragma unroll
                for (int ni = 0; ni < 4; ++ni)
                    MMA8(acc[mi][ni], a[mi], bf[ni][0], bf[ni][1]);
        }

        #pragma unroll
        for (int mi = 0; mi < 2; ++mi) {
            int t0 = wm0 + mi*16 + er;
            int t1 = t0 + 8;
            #pragma unroll
            for (int ni = 0; ni < 4; ++ni) {
                int s0 = wn0 + ni*8 + ec;
                float v0 = (s0     <= t0) ? tf32r(acc[mi][ni][0]) : 0.f;
                float v1 = (s0 + 1 <= t0) ? tf32r(acc[mi][ni][1]) : 0.f;
                float v2 = (s0     <= t1) ? tf32r(acc[mi][ni][2]) : 0.f;
                float v3 = (s0 + 1 <= t1) ? tf32r(acc[mi][ni][3]) : 0.f;
                *reinterpret_cast<float2*>(As + t0*LD + s0) = make_float2(v0, v1);
                *reinterpret_cast<float2*>(As + t1*LD + s0) = make_float2(v2, v3);
            }
        }
    }
    __syncthreads();

    // ---- denominators (split across 4 thread groups) + reload Bs ----
    {
        int t = tid & 127, p = tid >> 7;       // p = 0..3
        float r = 0.f;
        const int s0 = p * 32;
        #pragma unroll 8
        for (int s = s0; s < s0 + 32; ++s) r += As[t*LD + s];
        #pragma unroll 8
        for (int d = s0; d < s0 + 32; ++d) r = fmaf(Qs[t*LD + d], Np[d], r);
        atomicAdd(&rs[t], r);
    }
    const float* Mg = g_MpT + (size_t)(b*NCH + ch)*DD*DD;
    #pragma unroll
    for (int it = 0; it < 4; ++it) {
        int i = tid + it*512;
        int e = i >> 5, d4 = i & 31;
        reinterpret_cast<float4*>(Bs + e*LD)[d4] =
            tf32r4(reinterpret_cast<const float4*>(Mg)[(j0h + e)*32 + d4]);
    }
    const float* Vg = V + ((size_t)b*SS + ch*CC)*DD;
    #pragma unroll
    for (int it = 0; it < 4; ++it) {
        int i = tid + it*512;
        int d4h = i >> 7, t = i & 127;
        float4 v = tf32r4(reinterpret_cast<const float4*>(Vg)[t*32 + h*16 + d4h]);
        Bs[(64 + d4h*4+0)*LD + t] = v.x;
        Bs[(64 + d4h*4+1)*LD + t] = v.y;
        Bs[(64 + d4h*4+2)*LD + t] = v.z;
        Bs[(64 + d4h*4+3)*LD + t] = v.w;
    }
    __syncthreads();

    // ---- Phase B+C: C = phiQ @ Mprev_half + A_masked @ V_half  (128 x 64) ----
    {
        const int wn0 = (wid & 3) * 16;
        float acc[2][2][4];
        #pragma unroll
        for (int mi = 0; mi < 2; ++mi)
            #pragma unroll
            for (int ni = 0; ni < 2; ++ni)
                #pragma unroll
                for (int q = 0; q < 4; ++q) acc[mi][ni][q] = 0.f;

        #pragma unroll
        for (int k0 = 0; k0 < 128; k0 += 8) {      // phiQ @ MpT^T  (B rows 0-63)
            uint32_t a[2][4];
            #pragma unroll
            for (int mi = 0; mi < 2; ++mi)
                LDSMX4(a[mi], uQ + (uint32_t)(((wm0 + mi*16 + rowA)*LD + k0 + colA) << 2));
            uint32_t bf[2][2];
            #pragma unroll
            for (int ni = 0; ni < 2; ++ni)
                LDSMX2(bf[ni][0], bf[ni][1], uB + (uint32_t)(((wn0 + ni*8 + rowB)*LD + k0 + colB) << 2));
            #pragma unroll
            for (int mi = 0; mi < 2; ++mi)
                #pragma unroll
                for (int ni = 0; ni < 2; ++ni)
                    MMA8(acc[mi][ni], a[mi], bf[ni][0], bf[ni][1]);
        }
        #pragma unroll
        for (int k0 = 0; k0 < 128; k0 += 8) {      // A_masked @ V^T  (B rows 64-127)
            uint32_t a[2][4];
            #pragma unroll
            for (int mi = 0; mi < 2; ++mi)
                LDSMX4(a[mi], uA + (uint32_t)(((wm0 + mi*16 + rowA)*LD + k0 + colA) << 2));
            uint32_t bf[2][2];
            #pragma unroll
            for (int ni = 0; ni < 2; ++ni)
                LDSMX2(bf[ni][0], bf[ni][1], uB + (uint32_t)(((64 + wn0 + ni*8 + rowB)*LD + k0 + colB) << 2));
            #pragma unroll
            for (int mi = 0; mi < 2; ++mi)
                #pragma unroll
                for (int ni = 0; ni < 2; ++ni)
                    MMA8(acc[mi][ni], a[mi], bf[ni][0], bf[ni][1]);
        }

        #pragma unroll
        for (int mi = 0; mi < 2; ++mi) {
            int t0 = wm0 + mi*16 + er;
            float r0 = rs[t0];
            float inv0 = 1.f / (r0 + (r0 > 0.f ? 1e-6f : (r0 < 0.f ? -1e-6f : 0.f)));
            float r1 = rs[t0 + 8];
            float inv1 = 1.f / (r1 + (r1 > 0.f ? 1e-6f : (r1 < 0.f ? -1e-6f : 0.f)));
            size_t row0 = (size_t)b*SS + (size_t)ch*CC + t0;
            #pragma unroll
            for (int ni = 0; ni < 2; ++ni) {
                int col = j0h + wn0 + ni*8 + ec;
                *reinterpret_cast<float2*>(out + row0*DD + col) =
                    make_float2(acc[mi][ni][0]*inv0, acc[mi][ni][1]*inv0);
                *reinterpret_cast<float2*>(out + (row0 + 8)*DD + col) =
                    make_float2(acc[mi][ni][2]*inv1, acc[mi][ni][3]*inv1);
            }
        }
    }
}

// ============================================================================
extern "C" void kernel_launch(void* const* d_in, const int* in_sizes, int n_in,
                              void* d_out, int out_size) {
    const float* K = (const float*)d_in[0];
    const float* Q = (const float*)d_in[1];
    const float* V = (const float*)d_in[2];
    const float* W = (const float*)d_in[6];
    float* out = (float*)d_out;

    const int SMEM1 = (2*DD*LD + 128) * 4;      // ~136 KB
    const int SMEM2 = (2*DD*LD) * 4;            // ~135 KB
    const int SMEM4 = (3*DD*LD + 256) * 4;      // ~204 KB

    cudaFuncSetAttribute(phi_kernel,         cudaFuncAttributeMaxDynamicSharedMemorySize, SMEM1);
    cudaFuncSetAttribute(chunk_state_kernel, cudaFuncAttributeMaxDynamicSharedMemorySize, SMEM2);
    cudaFuncSetAttribute(output_kernel,      cudaFuncAttributeMaxDynamicSharedMemorySize, SMEM4);

    phi_kernel<<<128, 512, SMEM1>>>(K, Q, W);
    chunk_state_kernel<<<64, 512, SMEM2>>>(V);
    prefix_kernel<<<64, 256>>>();
    output_kernel<<<128, 512, SMEM4>>>(V, out);
}

// round 5
// speedup vs baseline: 2.7012x; 1.1550x over previous
#include <cuda_runtime.h>
#include <cuda_fp16.h>
#include <cstdint>

#define BB 4
#define SS 2048
#define DD 128
#define CC 128
#define NCH 16
#define LDH 136       // half-element row stride: 272 bytes, 16B-aligned rows, conflict-free ldmatrix

// ------------------- scratch (device globals; no allocs allowed) -------------------
__device__ __half g_phiK[BB*SS*DD];      // 2 MB
__device__ __half g_phiQ[BB*SS*DD];      // 2 MB
__device__ float  g_ScT [BB*NCH*DD*DD];  // fp32 chunk state (prefix precision)
__device__ float  g_nc  [BB*NCH*DD];
__device__ float  g_MpT [BB*NCH*DD*DD];
__device__ float  g_Np  [BB*NCH*DD];

// ------------------- helpers -------------------
__device__ __forceinline__ uint32_t sptr(const void* p){
    return (uint32_t)__cvta_generic_to_shared(p);
}

#define MMA16(d, a, b0v, b1v) \
    asm volatile("mma.sync.aligned.m16n8k16.row.col.f32.f16.f16.f32 " \
        "{%0,%1,%2,%3},{%4,%5,%6,%7},{%8,%9},{%0,%1,%2,%3};" \
        : "+f"(d[0]),"+f"(d[1]),"+f"(d[2]),"+f"(d[3]) \
        : "r"(a[0]),"r"(a[1]),"r"(a[2]),"r"(a[3]),"r"(b0v),"r"(b1v))

#define LDSMX4(r, addr) \
    asm volatile("ldmatrix.sync.aligned.m8n8.x4.shared.b16 {%0,%1,%2,%3},[%4];" \
        : "=r"(r[0]),"=r"(r[1]),"=r"(r[2]),"=r"(r[3]) : "r"(addr))

#define LDSMX2(r0, r1, addr) \
    asm volatile("ldmatrix.sync.aligned.m8n8.x2.shared.b16 {%0,%1},[%2];" \
        : "=r"(r0),"=r"(r1) : "r"(addr))

#define CP_ASYNC16(dst_u32, src_ptr) \
    asm volatile("cp.async.ca.shared.global [%0], [%1], 16;" :: "r"(dst_u32), "l"(src_ptr))
#define CP_COMMIT() asm volatile("cp.async.commit_group;")
#define CP_WAIT0()  asm volatile("cp.async.wait_group 0;")

// per-lane fragment offsets (element units).  A: m16k16 via ldsm.x4, B: n8k16 via ldsm.x2
#define FRAG_OFFS() \
    const int rowA = lane & 15;            \
    const int kofA = (lane >> 4) * 8;      \
    const int rowB = lane & 7;             \
    const int kofB = ((lane >> 3) & 1) * 8;\
    const int er   = lane >> 2;            \
    const int ec   = (lane & 3) * 2;

// ============================================================================
// Kernel 1: phi(X) = exp(-0.5*||x||)/sqrt(128) * exp(X @ W^T) -> half output
// grid = 128 (64 row-tiles x {K,Q}), 512 threads, warp tile 32x32
// ============================================================================
__global__ void __launch_bounds__(512, 1)
phi_kernel(const float* __restrict__ K, const float* __restrict__ Q,
           const float* __restrict__ W) {
    extern __shared__ char smraw[];
    __half* Xs    = (__half*)smraw;                    // [128][LDH]
    __half* Ws    = Xs + DD*LDH;                       // [128][LDH]
    float*  scale = (float*)(Ws + DD*LDH);             // [128]

    const int tid  = threadIdx.x;
    const int lane = tid & 31;
    const int wid  = tid >> 5;
    const int tileIdx = blockIdx.x & 63;
    const int sel     = blockIdx.x >> 6;
    const float* src  = sel ? Q : K;
    __half*      dst  = sel ? g_phiQ : g_phiK;
    const float* Xg   = src + (size_t)tileIdx * 128 * DD;

    if (tid < 128) scale[tid] = 0.f;
    __syncthreads();

    #pragma unroll
    for (int it = 0; it < 8; ++it) {
        int i = tid + it*512;
        int t = i >> 5, d4 = i & 31;
        float4 v = reinterpret_cast<const float4*>(Xg)[t*32 + d4];
        float ls = v.x*v.x + v.y*v.y + v.z*v.z + v.w*v.w;
        ls += __shfl_xor_sync(~0u, ls, 16);
        ls += __shfl_xor_sync(~0u, ls, 8);
        ls += __shfl_xor_sync(~0u, ls, 4);
        ls += __shfl_xor_sync(~0u, ls, 2);
        ls += __shfl_xor_sync(~0u, ls, 1);
        if (lane == 0) atomicAdd(&scale[t], ls);
        *reinterpret_cast<__half2*>(Xs + t*LDH + d4*4)     = __floats2half2_rn(v.x, v.y);
        *reinterpret_cast<__half2*>(Xs + t*LDH + d4*4 + 2) = __floats2half2_rn(v.z, v.w);
        float4 w = reinterpret_cast<const float4*>(W)[t*32 + d4];
        *reinterpret_cast<__half2*>(Ws + t*LDH + d4*4)     = __floats2half2_rn(w.x, w.y);
        *reinterpret_cast<__half2*>(Ws + t*LDH + d4*4 + 2) = __floats2half2_rn(w.z, w.w);
    }
    __syncthreads();
    if (tid < 128)
        scale[tid] = __expf(-0.5f * sqrtf(scale[tid])) * 0.08838834764831845f;
    __syncthreads();

    const int wm0 = (wid >> 2) * 32;
    const int wn0 = (wid & 3) * 32;
    FRAG_OFFS();
    const uint32_t uX = sptr(Xs), uW = sptr(Ws);

    float acc[2][4][4];
    #pragma unroll
    for (int mi = 0; mi < 2; ++mi)
        #pragma unroll
        for (int ni = 0; ni < 4; ++ni)
            #pragma unroll
            for (int q = 0; q < 4; ++q) acc[mi][ni][q] = 0.f;

    #pragma unroll
    for (int k0 = 0; k0 < 128; k0 += 16) {
        uint32_t a[2][4];
        #pragma unroll
        for (int mi = 0; mi < 2; ++mi)
            LDSMX4(a[mi], uX + (uint32_t)(((wm0 + mi*16 + rowA)*LDH + k0 + kofA) << 1));
        uint32_t b[4][2];
        #pragma unroll
        for (int ni = 0; ni < 4; ++ni)
            LDSMX2(b[ni][0], b[ni][1], uW + (uint32_t)(((wn0 + ni*8 + rowB)*LDH + k0 + kofB) << 1));
        #pragma unroll
        for (int mi = 0; mi < 2; ++mi)
            #pragma unroll
            for (int ni = 0; ni < 4; ++ni)
                MMA16(acc[mi][ni], a[mi], b[ni][0], b[ni][1]);
    }

    #pragma unroll
    for (int mi = 0; mi < 2; ++mi) {
        int r0 = wm0 + mi*16 + er;
        float s0 = scale[r0], s1 = scale[r0 + 8];
        size_t g0 = ((size_t)tileIdx*128 + r0) * DD;
        #pragma unroll
        for (int ni = 0; ni < 4; ++ni) {
            int col = wn0 + ni*8 + ec;
            *reinterpret_cast<__half2*>(dst + g0 + col) =
                __floats2half2_rn(s0*__expf(acc[mi][ni][0]), s0*__expf(acc[mi][ni][1]));
            *reinterpret_cast<__half2*>(dst + g0 + 8*DD + col) =
                __floats2half2_rn(s1*__expf(acc[mi][ni][2]), s1*__expf(acc[mi][ni][3]));
        }
    }
}

// ============================================================================
// Kernel 2: transposed chunk state ScT[e][d] = sum_t V[t][e]*phiK[t][d]
// grid = 64 chunks, 512 threads, warp tile 32x32
// ============================================================================
__global__ void __launch_bounds__(512, 1)
chunk_state_kernel(const float* __restrict__ V) {
    extern __shared__ char smraw[];
    __half* Vt = (__half*)smraw;     // [128][LDH]  V^T (rows e, cols t)
    __half* Kt = Vt + DD*LDH;        // [128][LDH]  phiK^T (rows d, cols t)

    const int tid = threadIdx.x, lane = tid & 31, wid = tid >> 5;
    const int b = blockIdx.x / NCH, ch = blockIdx.x % NCH;
    const __half* Kg = g_phiK + ((size_t)b*SS + ch*CC)*DD;
    const float*  Vg = V      + ((size_t)b*SS + ch*CC)*DD;

    #pragma unroll
    for (int it = 0; it < 8; ++it) {
        int i = tid + it*512;
        int d4 = i >> 7, t = i & 127;
        __half2 h0 = *reinterpret_cast<const __half2*>(Kg + t*128 + d4*4);
        __half2 h1 = *reinterpret_cast<const __half2*>(Kg + t*128 + d4*4 + 2);
        Kt[(d4*4+0)*LDH + t] = h0.x;
        Kt[(d4*4+1)*LDH + t] = h0.y;
        Kt[(d4*4+2)*LDH + t] = h1.x;
        Kt[(d4*4+3)*LDH + t] = h1.y;
        float4 v = reinterpret_cast<const float4*>(Vg)[t*32 + d4];
        Vt[(d4*4+0)*LDH + t] = __float2half_rn(v.x);
        Vt[(d4*4+1)*LDH + t] = __float2half_rn(v.y);
        Vt[(d4*4+2)*LDH + t] = __float2half_rn(v.z);
        Vt[(d4*4+3)*LDH + t] = __float2half_rn(v.w);
    }
    __syncthreads();

    const int wm0 = (wid >> 2) * 32;
    const int wn0 = (wid & 3) * 32;
    FRAG_OFFS();
    const uint32_t uV = sptr(Vt), uK = sptr(Kt);

    float acc[2][4][4];
    #pragma unroll
    for (int mi = 0; mi < 2; ++mi)
        #pragma unroll
        for (int ni = 0; ni < 4; ++ni)
            #pragma unroll
            for (int q = 0; q < 4; ++q) acc[mi][ni][q] = 0.f;

    #pragma unroll
    for (int k0 = 0; k0 < 128; k0 += 16) {
        uint32_t a[2][4];
        #pragma unroll
        for (int mi = 0; mi < 2; ++mi)
            LDSMX4(a[mi], uV + (uint32_t)(((wm0 + mi*16 + rowA)*LDH + k0 + kofA) << 1));
        uint32_t b[4][2];
        #pragma unroll
        for (int ni = 0; ni < 4; ++ni)
            LDSMX2(b[ni][0], b[ni][1], uK + (uint32_t)(((wn0 + ni*8 + rowB)*LDH + k0 + kofB) << 1));
        #pragma unroll
        for (int mi = 0; mi < 2; ++mi)
            #pragma unroll
            for (int ni = 0; ni < 4; ++ni)
                MMA16(acc[mi][ni], a[mi], b[ni][0], b[ni][1]);
    }

    float* Sg = g_ScT + (size_t)(b*NCH + ch)*DD*DD;
    #pragma unroll
    for (int mi = 0; mi < 2; ++mi) {
        int r0 = wm0 + mi*16 + er;
        #pragma unroll
        for (int ni = 0; ni < 4; ++ni) {
            int col = wn0 + ni*8 + ec;
            *reinterpret_cast<float2*>(Sg + (size_t)r0*DD + col)     = make_float2(acc[mi][ni][0], acc[mi][ni][1]);
            *reinterpret_cast<float2*>(Sg + (size_t)(r0+8)*DD + col) = make_float2(acc[mi][ni][2], acc[mi][ni][3]);
        }
    }

    if (tid < 128) {
        float s = 0.f;
        #pragma unroll 8
        for (int t = 0; t < 128; ++t) s += __half2float(Kt[tid*LDH + t]);
        g_nc[(size_t)(b*NCH + ch)*DD + tid] = s;
    }
}

// ============================================================================
// Kernel 3: exclusive prefix over chunks (elementwise fp32).  grid=64
// ============================================================================
__global__ void prefix_kernel() {
    const int b = blockIdx.x >> 4, slab = blockIdx.x & 15;
    const size_t base = (size_t)b*NCH*DD*DD;
    const int e0 = slab*1024 + threadIdx.x;
    float acc[4] = {0.f, 0.f, 0.f, 0.f};
    for (int c = 0; c < NCH; ++c) {
        size_t off = base + (size_t)c*DD*DD;
        #pragma unroll
        for (int k = 0; k < 4; ++k) {
            g_MpT[off + e0 + k*256] = acc[k];
            acc[k] += g_ScT[off + e0 + k*256];
        }
    }
    if (slab == 0 && threadIdx.x < 128) {
        float an = 0.f;
        int i = threadIdx.x;
        for (int c = 0; c < NCH; ++c) {
            g_Np[(size_t)(b*NCH + c)*DD + i] = an;
            an += g_nc[(size_t)(b*NCH + c)*DD + i];
        }
    }
}

// ============================================================================
// Kernel 4: per-chunk output, split on output columns.
// grid = 128 (64 chunks x 2 j-halves), 512 threads
// ============================================================================
__global__ void __launch_bounds__(512, 1)
output_kernel(const float* __restrict__ V, float* __restrict__ out) {
    extern __shared__ char smraw[];
    __half* Qs = (__half*)smraw;         // [128][LDH] phiQ
    __half* Bs = Qs + DD*LDH;            // [128][LDH] phiK -> Mp(0-63)+V^T(64-127)
    __half* As = Bs + DD*LDH;            // [128][LDH] masked A [t][s]
    float*  rs = (float*)(As + DD*LDH);  // [128]
    float*  Np = rs + 128;               // [128]
    float*  stageM = Np + 128;           // [64*128] fp32 Mp half-tile
    float*  stageV = stageM + 64*128;    // [128*64] fp32 V slice

    const int tid = threadIdx.x, lane = tid & 31, wid = tid >> 5;
    const int chunk = blockIdx.x >> 1, h = blockIdx.x & 1;
    const int b = chunk / NCH, ch = chunk % NCH;
    const int j0h = h * 64;

    const __half* Qg = g_phiQ + ((size_t)b*SS + ch*CC)*DD;
    const __half* Kg = g_phiK + ((size_t)b*SS + ch*CC)*DD;
    const float*  Mg = g_MpT + (size_t)(b*NCH + ch)*DD*DD + (size_t)j0h*DD;
    const float*  Vg = V + ((size_t)b*SS + ch*CC)*DD + j0h;

    // prefetch Mprev half-tile + V slice into fp32 staging (overlaps phase A)
    {
        const uint32_t uSM = sptr(stageM), uSV = sptr(stageV);
        #pragma unroll
        for (int it = 0; it < 4; ++it) {
            int c = tid + it*512;                     // 0..2047
            CP_ASYNC16(uSM + c*16, Mg + (c >> 5)*128 + (c & 31)*4);
            CP_ASYNC16(uSV + c*16, Vg + (c >> 4)*128 + (c & 15)*4);
        }
        CP_COMMIT();
    }

    if (tid < 128) {
        rs[tid] = 0.f;
        Np[tid] = g_Np[(size_t)(b*NCH + ch)*DD + tid];
    }
    #pragma unroll
    for (int it = 0; it < 4; ++it) {
        int i = tid + it*512;
        int t = i >> 4, c8 = i & 15;
        *reinterpret_cast<uint4*>(Qs + t*LDH + c8*8) =
            *reinterpret_cast<const uint4*>(Qg + t*128 + c8*8);
        *reinterpret_cast<uint4*>(Bs + t*LDH + c8*8) =
            *reinterpret_cast<const uint4*>(Kg + t*128 + c8*8);
    }
    __syncthreads();

    const int wm0 = (wid >> 2) * 32;
    FRAG_OFFS();
    const uint32_t uQ = sptr(Qs), uB = sptr(Bs), uA = sptr(As);

    // ---- Phase A: A[t][s] = phiQ . phiK (128x128), masked half store ----
    {
        const int wn0 = (wid & 3) * 32;
        float acc[2][4][4];
        #pragma unroll
        for (int mi = 0; mi < 2; ++mi)
            #pragma unroll
            for (int ni = 0; ni < 4; ++ni)
                #pragma unroll
                for (int q = 0; q < 4; ++q) acc[mi][ni][q] = 0.f;

        #pragma unroll
        for (int k0 = 0; k0 < 128; k0 += 16) {
            uint32_t a[2][4];
            #pragma unroll
            for (int mi = 0; mi < 2; ++mi)
                LDSMX4(a[mi], uQ + (uint32_t)(((wm0 + mi*16 + rowA)*LDH + k0 + kofA) << 1));
            uint32_t bf[4][2];
            #pragma unroll
            for (int ni = 0; ni < 4; ++ni)
                LDSMX2(bf[ni][0], bf[ni][1], uB + (uint32_t)(((wn0 + ni*8 + rowB)*LDH + k0 + kofB) << 1));
            #pragma unroll
            for (int mi = 0; mi < 2; ++mi)
                #pragma unroll
                for (int ni = 0; ni < 4; ++ni)
                    MMA16(acc[mi][ni], a[mi], bf[ni][0], bf[ni][1]);
        }

        #pragma unroll
        for (int mi = 0; mi < 2; ++mi) {
            int t0 = wm0 + mi*16 + er;
            int t1 = t0 + 8;
            #pragma unroll
            for (int ni = 0; ni < 4; ++ni) {
                int s0 = wn0 + ni*8 + ec;
                float v0 = (s0     <= t0) ? acc[mi][ni][0] : 0.f;
                float v1 = (s0 + 1 <= t0) ? acc[mi][ni][1] : 0.f;
                float v2 = (s0     <= t1) ? acc[mi][ni][2] : 0.f;
                float v3 = (s0 + 1 <= t1) ? acc[mi][ni][3] : 0.f;
                *reinterpret_cast<__half2*>(As + t0*LDH + s0) = __floats2half2_rn(v0, v1);
                *reinterpret_cast<__half2*>(As + t1*LDH + s0) = __floats2half2_rn(v2, v3);
            }
        }
    }
    __syncthreads();

    // ---- denominators (4 partial groups) ----
    {
        int t = tid & 127, p = tid >> 7;       // p = 0..3
        float r = 0.f;
        const int s0 = p * 32;
        #pragma unroll 8
        for (int s = s0; s < s0 + 32; s += 2) {
            float2 f = __half22float2(*reinterpret_cast<__half2*>(As + t*LDH + s));
            r += f.x + f.y;
        }
        #pragma unroll 8
        for (int d = s0; d < s0 + 32; ++d)
            r = fmaf(__half2float(Qs[t*LDH + d]), Np[d], r);
        atomicAdd(&rs[t], r);
    }
    CP_WAIT0();
    __syncthreads();

    // ---- convert staged Mp + V^T into Bs (half) ----
    #pragma unroll
    for (int it = 0; it < 4; ++it) {
        int i = tid + it*512;
        int e = i >> 5, d4 = i & 31;
        float4 m = reinterpret_cast<const float4*>(stageM)[e*32 + d4];
        *reinterpret_cast<__half2*>(Bs + e*LDH + d4*4)     = __floats2half2_rn(m.x, m.y);
        *reinterpret_cast<__half2*>(Bs + e*LDH + d4*4 + 2) = __floats2half2_rn(m.z, m.w);
    }
    #pragma unroll
    for (int it = 0; it < 4; ++it) {
        int i = tid + it*512;
        int d4h = i >> 7, t = i & 127;
        float4 v = reinterpret_cast<const float4*>(stageV)[t*16 + d4h];
        Bs[(64 + d4h*4+0)*LDH + t] = __float2half_rn(v.x);
        Bs[(64 + d4h*4+1)*LDH + t] = __float2half_rn(v.y);
        Bs[(64 + d4h*4+2)*LDH + t] = __float2half_rn(v.z);
        Bs[(64 + d4h*4+3)*LDH + t] = __float2half_rn(v.w);
    }
    __syncthreads();

    // ---- Phase B+C: C = phiQ @ Mp_half^T + A_masked @ V_half^T  (128 x 64) ----
    {
        const int wn0 = (wid & 3) * 16;
        float acc[2][2][4];
        #pragma unroll
        for (int mi = 0; mi < 2; ++mi)
            #pragma unroll
            for (int ni = 0; ni < 2; ++ni)
                #pragma unroll
                for (int q = 0; q < 4; ++q) acc[mi][ni][q] = 0.f;

        #pragma unroll
        for (int k0 = 0; k0 < 128; k0 += 16) {     // phiQ @ Mp  (B rows 0-63)
            uint32_t a[2][4];
            #pragma unroll
            for (int mi = 0; mi < 2; ++mi)
                LDSMX4(a[mi], uQ + (uint32_t)(((wm0 + mi*16 + rowA)*LDH + k0 + kofA) << 1));
            uint32_t bf[2][2];
            #pragma unroll
            for (int ni = 0; ni < 2; ++ni)
                LDSMX2(bf[ni][0], bf[ni][1], uB + (uint32_t)(((wn0 + ni*8 + rowB)*LDH + k0 + kofB) << 1));
            #pragma unroll
            for (int mi = 0; mi < 2; ++mi)
                #pragma unroll
                for (int ni = 0; ni < 2; ++ni)
                    MMA16(acc[mi][ni], a[mi], bf[ni][0], bf[ni][1]);
        }
        #pragma unroll
        for (int k0 = 0; k0 < 128; k0 += 16) {     // A_masked @ V^T  (B rows 64-127)
            uint32_t a[2][4];
            #pragma unroll
            for (int mi = 0; mi < 2; ++mi)
                LDSMX4(a[mi], uA + (uint32_t)(((wm0 + mi*16 + rowA)*LDH + k0 + kofA) << 1));
            uint32_t bf[2][2];
            #pragma unroll
            for (int ni = 0; ni < 2; ++ni)
                LDSMX2(bf[ni][0], bf[ni][1], uB + (uint32_t)(((64 + wn0 + ni*8 + rowB)*LDH + k0 + kofB) << 1));
            #pragma unroll
            for (int mi = 0; mi < 2; ++mi)
                #pragma unroll
                for (int ni = 0; ni < 2; ++ni)
                    MMA16(acc[mi][ni], a[mi], bf[ni][0], bf[ni][1]);
        }

        #pragma unroll
        for (int mi = 0; mi < 2; ++mi) {
            int t0 = wm0 + mi*16 + er;
            float r0 = rs[t0];
            float inv0 = 1.f / (r0 + (r0 > 0.f ? 1e-6f : (r0 < 0.f ? -1e-6f : 0.f)));
            float r1 = rs[t0 + 8];
            float inv1 = 1.f / (r1 + (r1 > 0.f ? 1e-6f : (r1 < 0.f ? -1e-6f : 0.f)));
            size_t row0 = (size_t)b*SS + (size_t)ch*CC + t0;
            #pragma unroll
            for (int ni = 0; ni < 2; ++ni) {
                int col = j0h + wn0 + ni*8 + ec;
                *reinterpret_cast<float2*>(out + row0*DD + col) =
                    make_float2(acc[mi][ni][0]*inv0, acc[mi][ni][1]*inv0);
                *reinterpret_cast<float2*>(out + (row0 + 8)*DD + col) =
                    make_float2(acc[mi][ni][2]*inv1, acc[mi][ni][3]*inv1);
            }
        }
    }
}

// ============================================================================
extern "C" void kernel_launch(void* const* d_in, const int* in_sizes, int n_in,
                              void* d_out, int out_size) {
    const float* K = (const float*)d_in[0];
    const float* Q = (const float*)d_in[1];
    const float* V = (const float*)d_in[2];
    const float* W = (const float*)d_in[6];
    float* out = (float*)d_out;

    const int SMEM1 = 2*DD*LDH*2 + 512;                       // ~70 KB
    const int SMEM2 = 2*DD*LDH*2;                             // ~69 KB
    const int SMEM4 = 3*DD*LDH*2 + 1024 + 2*64*128*4;         // ~167 KB

    cudaFuncSetAttribute(phi_kernel,         cudaFuncAttributeMaxDynamicSharedMemorySize, SMEM1);
    cudaFuncSetAttribute(chunk_state_kernel, cudaFuncAttributeMaxDynamicSharedMemorySize, SMEM2);
    cudaFuncSetAttribute(output_kernel,      cudaFuncAttributeMaxDynamicSharedMemorySize, SMEM4);

    phi_kernel<<<128, 512, SMEM1>>>(K, Q, W);
    chunk_state_kernel<<<64, 512, SMEM2>>>(V);
    prefix_kernel<<<64, 256>>>();
    output_kernel<<<128, 512, SMEM4>>>(V, out);
}

// round 6
// speedup vs baseline: 3.0337x; 1.1231x over previous
#include <cuda_runtime.h>
#include <cuda_fp16.h>
#include <cstdint>

#define BB 4
#define SS 2048
#define DD 128
#define CC 128
#define NCH 16
#define LDH 136       // half-element row stride: 272B rows, 16B aligned, conflict-free ldmatrix

// ------------------- scratch (device globals; no allocs allowed) -------------------
__device__ __half g_phiK[BB*SS*DD];      // 2 MB
__device__ __half g_phiQ[BB*SS*DD];      // 2 MB
__device__ __half g_Vth [BB*SS*DD];      // 2 MB  V^T per chunk, half: [(b,ch)][e][t]
__device__ float  g_ScT [BB*NCH*DD*DD];  // 4 MB  fp32 chunk state
__device__ float  g_nc  [BB*NCH*DD];
__device__ __half g_MpTh[BB*NCH*DD*DD];  // 2 MB  exclusive prefix of ScT, half
__device__ float  g_Np  [BB*NCH*DD];

// ------------------- helpers -------------------
__device__ __forceinline__ uint32_t sptr(const void* p){
    return (uint32_t)__cvta_generic_to_shared(p);
}

#define MMA16(d, a, b0v, b1v) \
    asm volatile("mma.sync.aligned.m16n8k16.row.col.f32.f16.f16.f32 " \
        "{%0,%1,%2,%3},{%4,%5,%6,%7},{%8,%9},{%0,%1,%2,%3};" \
        : "+f"(d[0]),"+f"(d[1]),"+f"(d[2]),"+f"(d[3]) \
        : "r"(a[0]),"r"(a[1]),"r"(a[2]),"r"(a[3]),"r"(b0v),"r"(b1v))

#define LDSMX4(r, addr) \
    asm volatile("ldmatrix.sync.aligned.m8n8.x4.shared.b16 {%0,%1,%2,%3},[%4];" \
        : "=r"(r[0]),"=r"(r[1]),"=r"(r[2]),"=r"(r[3]) : "r"(addr))

#define LDSMX2(r0, r1, addr) \
    asm volatile("ldmatrix.sync.aligned.m8n8.x2.shared.b16 {%0,%1},[%2];" \
        : "=r"(r0),"=r"(r1) : "r"(addr))

// per-lane fragment offsets (element units). A: m16k16 via ldsm.x4, B: n8k16 via ldsm.x2
#define FRAG_OFFS() \
    const int rowA = lane & 15;            \
    const int kofA = (lane >> 4) * 8;      \
    const int rowB = lane & 7;             \
    const int kofB = ((lane >> 3) & 1) * 8;\
    const int er   = lane >> 2;            \
    const int ec   = (lane & 3) * 2;

// fragment loaders (32-row A tile = 2 x m16; B tiles of 4 or 2 n8 rows)
#define LOADA2(dst, u, r0, k0) { \
    LDSMX4(dst[0], (u) + (uint32_t)((((r0) + rowA)*LDH + (k0) + kofA) << 1)); \
    LDSMX4(dst[1], (u) + (uint32_t)((((r0) + 16 + rowA)*LDH + (k0) + kofA) << 1)); }

#define LOADB4(dst, u, n0, k0) { \
    LDSMX2(dst[0][0], dst[0][1], (u) + (uint32_t)((((n0) +  0 + rowB)*LDH + (k0) + kofB) << 1)); \
    LDSMX2(dst[1][0], dst[1][1], (u) + (uint32_t)((((n0) +  8 + rowB)*LDH + (k0) + kofB) << 1)); \
    LDSMX2(dst[2][0], dst[2][1], (u) + (uint32_t)((((n0) + 16 + rowB)*LDH + (k0) + kofB) << 1)); \
    LDSMX2(dst[3][0], dst[3][1], (u) + (uint32_t)((((n0) + 24 + rowB)*LDH + (k0) + kofB) << 1)); }

#define LOADB2(dst, u, n0, k0) { \
    LDSMX2(dst[0][0], dst[0][1], (u) + (uint32_t)((((n0) + rowB)*LDH + (k0) + kofB) << 1)); \
    LDSMX2(dst[1][0], dst[1][1], (u) + (uint32_t)((((n0) + 8 + rowB)*LDH + (k0) + kofB) << 1)); }

// pipelined 128-k GEMM, 32x32 warp tile (acc[2][4][4])
#define GEMM_PIPE_24(acc, uA_, rA0, uB_, nB0) { \
    uint32_t a_[2][2][4]; uint32_t b_[2][4][2]; \
    LOADA2(a_[0], uA_, rA0, 0); LOADB4(b_[0], uB_, nB0, 0); \
    _Pragma("unroll") \
    for (int kk = 0; kk < 8; ++kk) { \
        const int cur = kk & 1, nxt = cur ^ 1; \
        if (kk < 7) { LOADA2(a_[nxt], uA_, rA0, (kk+1)*16); LOADB4(b_[nxt], uB_, nB0, (kk+1)*16); } \
        _Pragma("unroll") \
        for (int mi = 0; mi < 2; ++mi) \
            _Pragma("unroll") \
            for (int ni = 0; ni < 4; ++ni) \
                MMA16(acc[mi][ni], a_[cur][mi], b_[cur][ni][0], b_[cur][ni][1]); \
    } }

// ============================================================================
// Kernel 1 (fused): phi for K & Q; K-blocks additionally compute chunk state
// ScT = V^T phiK, nc, and write V^T half to gmem.
// grid = 128 (64 tiles x {K,Q}), 512 threads, warp tile 32x32
// ============================================================================
__global__ void __launch_bounds__(512, 1)
phi_state_kernel(const float* __restrict__ K, const float* __restrict__ Q,
                 const float* __restrict__ W, const float* __restrict__ V) {
    extern __shared__ char smraw[];
    __half* Xs    = (__half*)smraw;            // [128][LDH]  (later: phiK^T)
    __half* Ws    = Xs + DD*LDH;               // [128][LDH]  (later: V^T)
    float*  scale = (float*)(Ws + DD*LDH);     // [128]

    const int tid  = threadIdx.x;
    const int lane = tid & 31;
    const int wid  = tid >> 5;
    const int tileIdx = blockIdx.x & 63;
    const int sel     = blockIdx.x >> 6;
    const float* src  = sel ? Q : K;
    __half*      dst  = sel ? g_phiQ : g_phiK;
    const float* Xg   = src + (size_t)tileIdx * 128 * DD;

    if (tid < 128) scale[tid] = 0.f;
    __syncthreads();

    #pragma unroll
    for (int it = 0; it < 8; ++it) {
        int i = tid + it*512;
        int t = i >> 5, d4 = i & 31;
        float4 v = reinterpret_cast<const float4*>(Xg)[t*32 + d4];
        float ls = v.x*v.x + v.y*v.y + v.z*v.z + v.w*v.w;
        ls += __shfl_xor_sync(~0u, ls, 16);
        ls += __shfl_xor_sync(~0u, ls, 8);
        ls += __shfl_xor_sync(~0u, ls, 4);
        ls += __shfl_xor_sync(~0u, ls, 2);
        ls += __shfl_xor_sync(~0u, ls, 1);
        if (lane == 0) atomicAdd(&scale[t], ls);
        *reinterpret_cast<__half2*>(Xs + t*LDH + d4*4)     = __floats2half2_rn(v.x, v.y);
        *reinterpret_cast<__half2*>(Xs + t*LDH + d4*4 + 2) = __floats2half2_rn(v.z, v.w);
        float4 w = reinterpret_cast<const float4*>(W)[t*32 + d4];
        *reinterpret_cast<__half2*>(Ws + t*LDH + d4*4)     = __floats2half2_rn(w.x, w.y);
        *reinterpret_cast<__half2*>(Ws + t*LDH + d4*4 + 2) = __floats2half2_rn(w.z, w.w);
    }
    __syncthreads();
    if (tid < 128)
        scale[tid] = __expf(-0.5f * sqrtf(scale[tid])) * 0.08838834764831845f;
    __syncthreads();

    const int wm0 = (wid >> 2) * 32;
    const int wn0 = (wid & 3) * 32;
    FRAG_OFFS();
    const uint32_t uX = sptr(Xs), uW = sptr(Ws);

    float acc[2][4][4];
    #pragma unroll
    for (int mi = 0; mi < 2; ++mi)
        #pragma unroll
        for (int ni = 0; ni < 4; ++ni)
            #pragma unroll
            for (int q = 0; q < 4; ++q) acc[mi][ni][q] = 0.f;

    GEMM_PIPE_24(acc, uX, wm0, uW, wn0);

    // compute phi outputs (half2 pairs), keep in regs
    __half2 oph[2][4][2];
    #pragma unroll
    for (int mi = 0; mi < 2; ++mi) {
        int r0 = wm0 + mi*16 + er;
        float s0 = scale[r0], s1 = scale[r0 + 8];
        #pragma unroll
        for (int ni = 0; ni < 4; ++ni) {
            oph[mi][ni][0] = __floats2half2_rn(s0*__expf(acc[mi][ni][0]), s0*__expf(acc[mi][ni][1]));
            oph[mi][ni][1] = __floats2half2_rn(s1*__expf(acc[mi][ni][2]), s1*__expf(acc[mi][ni][3]));
        }
    }
    __syncthreads();   // all warps done reading Xs/Ws

    // write phi to gmem
    #pragma unroll
    for (int mi = 0; mi < 2; ++mi) {
        int r0 = wm0 + mi*16 + er;
        size_t g0 = ((size_t)tileIdx*128 + r0) * DD;
        #pragma unroll
        for (int ni = 0; ni < 4; ++ni) {
            int col = wn0 + ni*8 + ec;
            *reinterpret_cast<__half2*>(dst + g0 + col)        = oph[mi][ni][0];
            *reinterpret_cast<__half2*>(dst + g0 + 8*DD + col) = oph[mi][ni][1];
        }
    }

    if (sel == 0) {
        // ---- chunk-state phase: phiK^T -> Xs, V^T -> Ws ----
        const int b = tileIdx / NCH, ch = tileIdx % NCH;

        #pragma unroll
        for (int mi = 0; mi < 2; ++mi) {
            int t0 = wm0 + mi*16 + er;
            #pragma unroll
            for (int ni = 0; ni < 4; ++ni) {
                int col = wn0 + ni*8 + ec;
                Xs[(col  )*LDH + t0]     = oph[mi][ni][0].x;
                Xs[(col+1)*LDH + t0]     = oph[mi][ni][0].y;
                Xs[(col  )*LDH + t0 + 8] = oph[mi][ni][1].x;
                Xs[(col+1)*LDH + t0 + 8] = oph[mi][ni][1].y;
            }
        }

        const float* Vg = V + ((size_t)b*SS + ch*CC)*DD;
        __half* Vthg = g_Vth + (size_t)tileIdx*CC*DD;
        #pragma unroll
        for (int it = 0; it < 8; ++it) {
            int i = tid + it*512;
            int d4 = i >> 7, t = i & 127;
            float4 v = reinterpret_cast<const float4*>(Vg)[t*32 + d4];
            __half h0 = __float2half_rn(v.x), h1 = __float2half_rn(v.y);
            __half h2 = __float2half_rn(v.z), h3 = __float2half_rn(v.w);
            Ws[(d4*4+0)*LDH + t] = h0;
            Ws[(d4*4+1)*LDH + t] = h1;
            Ws[(d4*4+2)*LDH + t] = h2;
            Ws[(d4*4+3)*LDH + t] = h3;
            Vthg[(d4*4+0)*128 + t] = h0;
            Vthg[(d4*4+1)*128 + t] = h1;
            Vthg[(d4*4+2)*128 + t] = h2;
            Vthg[(d4*4+3)*128 + t] = h3;
        }
        __syncthreads();

        // GEMM2: ScT[e][d] = sum_t Vt[e][t] * phiKt[d][t]
        float acc2[2][4][4];
        #pragma unroll
        for (int mi = 0; mi < 2; ++mi)
            #pragma unroll
            for (int ni = 0; ni < 4; ++ni)
                #pragma unroll
                for (int q = 0; q < 4; ++q) acc2[mi][ni][q] = 0.f;

        GEMM_PIPE_24(acc2, uW, wm0, uX, wn0);

        float* Sg = g_ScT + (size_t)tileIdx*DD*DD;
        #pragma unroll
        for (int mi = 0; mi < 2; ++mi) {
            int r0 = wm0 + mi*16 + er;
            #pragma unroll
            for (int ni = 0; ni < 4; ++ni) {
                int col = wn0 + ni*8 + ec;
                *reinterpret_cast<float2*>(Sg + (size_t)r0*DD + col)     = make_float2(acc2[mi][ni][0], acc2[mi][ni][1]);
                *reinterpret_cast<float2*>(Sg + (size_t)(r0+8)*DD + col) = make_float2(acc2[mi][ni][2], acc2[mi][ni][3]);
            }
        }

        if (tid < 128) {
            float s = 0.f;
            #pragma unroll 8
            for (int t = 0; t < 128; ++t) s += __half2float(Xs[tid*LDH + t]);
            g_nc[(size_t)tileIdx*DD + tid] = s;
        }
    }
}

// ============================================================================
// Kernel 2: exclusive prefix over chunks (fp32 accum), emit half MpT.
// grid = 256 (b*64 + slab), 256 threads, 1 element/thread
// ============================================================================
__global__ void prefix_kernel() {
    const int b = blockIdx.x >> 6, slab = blockIdx.x & 63;
    const size_t base = (size_t)b*NCH*DD*DD;
    const int e0 = slab*256 + threadIdx.x;
    float acc = 0.f;
    for (int c = 0; c < NCH; ++c) {
        size_t off = base + (size_t)c*DD*DD;
        g_MpTh[off + e0] = __float2half_rn(acc);
        acc += g_ScT[off + e0];
    }
    if (slab == 0 && threadIdx.x < 128) {
        float an = 0.f;
        int i = threadIdx.x;
        for (int c = 0; c < NCH; ++c) {
            g_Np[(size_t)(b*NCH + c)*DD + i] = an;
            an += g_nc[(size_t)(b*NCH + c)*DD + i];
        }
    }
}

// ============================================================================
// Kernel 3: per-chunk output, split on output columns.
// grid = 128 (64 chunks x 2 j-halves), 512 threads
// ============================================================================
__global__ void __launch_bounds__(512, 1)
output_kernel(float* __restrict__ out) {
    extern __shared__ char smraw[];
    __half* Qs = (__half*)smraw;         // [128][LDH] phiQ
    __half* Bs = Qs + DD*LDH;            // [128][LDH] phiK -> Mp(0-63)+V^T(64-127)
    __half* As = Bs + DD*LDH;            // [128][LDH] masked A [t][s]
    float*  rs = (float*)(As + DD*LDH);  // [128]
    float*  Np = rs + 128;               // [128]

    const int tid = threadIdx.x, lane = tid & 31, wid = tid >> 5;
    const int chunk = blockIdx.x >> 1, h = blockIdx.x & 1;
    const int b = chunk / NCH, ch = chunk % NCH;
    const int j0h = h * 64;

    const __half* Qg = g_phiQ + (size_t)chunk*CC*DD;
    const __half* Kg = g_phiK + (size_t)chunk*CC*DD;

    if (tid < 128) {
        rs[tid] = 0.f;
        Np[tid] = g_Np[(size_t)chunk*DD + tid];
    }
    #pragma unroll
    for (int it = 0; it < 4; ++it) {
        int i = tid + it*512;
        int t = i >> 4, c8 = i & 15;
        *reinterpret_cast<uint4*>(Qs + t*LDH + c8*8) =
            *reinterpret_cast<const uint4*>(Qg + t*128 + c8*8);
        *reinterpret_cast<uint4*>(Bs + t*LDH + c8*8) =
            *reinterpret_cast<const uint4*>(Kg + t*128 + c8*8);
    }
    __syncthreads();

    const int wm0 = (wid >> 2) * 32;
    FRAG_OFFS();
    const uint32_t uQ = sptr(Qs), uB = sptr(Bs), uA = sptr(As);

    // ---- Phase A: A[t][s] = phiQ . phiK (128x128), masked half store ----
    {
        const int wn0 = (wid & 3) * 32;
        float acc[2][4][4];
        #pragma unroll
        for (int mi = 0; mi < 2; ++mi)
            #pragma unroll
            for (int ni = 0; ni < 4; ++ni)
                #pragma unroll
                for (int q = 0; q < 4; ++q) acc[mi][ni][q] = 0.f;

        GEMM_PIPE_24(acc, uQ, wm0, uB, wn0);

        #pragma unroll
        for (int mi = 0; mi < 2; ++mi) {
            int t0 = wm0 + mi*16 + er;
            int t1 = t0 + 8;
            #pragma unroll
            for (int ni = 0; ni < 4; ++ni) {
                int s0 = wn0 + ni*8 + ec;
                float v0 = (s0     <= t0) ? acc[mi][ni][0] : 0.f;
                float v1 = (s0 + 1 <= t0) ? acc[mi][ni][1] : 0.f;
                float v2 = (s0     <= t1) ? acc[mi][ni][2] : 0.f;
                float v3 = (s0 + 1 <= t1) ? acc[mi][ni][3] : 0.f;
                *reinterpret_cast<__half2*>(As + t0*LDH + s0) = __floats2half2_rn(v0, v1);
                *reinterpret_cast<__half2*>(As + t1*LDH + s0) = __floats2half2_rn(v2, v3);
            }
        }
    }
    __syncthreads();

    // ---- denominators (4 partial groups) + reload Bs (direct half copies) ----
    {
        int t = tid & 127, p = tid >> 7;       // p = 0..3
        float r = 0.f;
        const int s0 = p * 32;
        #pragma unroll 8
        for (int s = s0; s < s0 + 32; s += 2) {
            float2 f = __half22float2(*reinterpret_cast<__half2*>(As + t*LDH + s));
            r += f.x + f.y;
        }
        #pragma unroll 8
        for (int d = s0; d < s0 + 32; ++d)
            r = fmaf(__half2float(Qs[t*LDH + d]), Np[d], r);
        atomicAdd(&rs[t], r);
    }
    {
        const __half* Mg = g_MpTh + (size_t)chunk*DD*DD + (size_t)j0h*DD;
        const __half* Vg = g_Vth  + (size_t)chunk*CC*DD + (size_t)j0h*DD;
        #pragma unroll
        for (int it = 0; it < 2; ++it) {
            int i = tid + it*512;
            int e = i >> 4, c8 = i & 15;
            *reinterpret_cast<uint4*>(Bs + e*LDH + c8*8) =
                *reinterpret_cast<const uint4*>(Mg + e*128 + c8*8);
            *reinterpret_cast<uint4*>(Bs + (64 + e)*LDH + c8*8) =
                *reinterpret_cast<const uint4*>(Vg + e*128 + c8*8);
        }
    }
    __syncthreads();

    // ---- Phase B+C: C = phiQ @ Mp_half^T + A_masked @ V_half^T (128 x 64) ----
    {
        const int wn0 = (wid & 3) * 16;
        float acc[2][2][4];
        #pragma unroll
        for (int mi = 0; mi < 2; ++mi)
            #pragma unroll
            for (int ni = 0; ni < 2; ++ni)
                #pragma unroll
                for (int q = 0; q < 4; ++q) acc[mi][ni][q] = 0.f;

        uint32_t a_[2][2][4]; uint32_t b_[2][2][2];
        LOADA2(a_[0], uQ, wm0, 0);
        LOADB2(b_[0], uB, wn0, 0);
        #pragma unroll
        for (int kk = 0; kk < 16; ++kk) {
            const int cur = kk & 1, nxt = cur ^ 1;
            const int k1 = kk + 1;
            if (k1 < 8) {
                LOADA2(a_[nxt], uQ, wm0, k1*16);
                LOADB2(b_[nxt], uB, wn0, k1*16);
            } else if (k1 < 16) {
                LOADA2(a_[nxt], uA, wm0, (k1-8)*16);
                LOADB2(b_[nxt], uB, 64 + wn0, (k1-8)*16);
            }
            #pragma unroll
            for (int mi = 0; mi < 2; ++mi)
                #pragma unroll
                for (int ni = 0; ni < 2; ++ni)
                    MMA16(acc[mi][ni], a_[cur][mi], b_[cur][ni][0], b_[cur][ni][1]);
        }

        #pragma unroll
        for (int mi = 0; mi < 2; ++mi) {
            int t0 = wm0 + mi*16 + er;
            float r0 = rs[t0];
            float inv0 = 1.f / (r0 + (r0 > 0.f ? 1e-6f : (r0 < 0.f ? -1e-6f : 0.f)));
            float r1 = rs[t0 + 8];
            float inv1 = 1.f / (r1 + (r1 > 0.f ? 1e-6f : (r1 < 0.f ? -1e-6f : 0.f)));
            size_t row0 = (size_t)b*SS + (size_t)ch*CC + t0;
            #pragma unroll
            for (int ni = 0; ni < 2; ++ni) {
                int col = j0h + wn0 + ni*8 + ec;
                *reinterpret_cast<float2*>(out + row0*DD + col) =
                    make_float2(acc[mi][ni][0]*inv0, acc[mi][ni][1]*inv0);
                *reinterpret_cast<float2*>(out + (row0 + 8)*DD + col) =
                    make_float2(acc[mi][ni][2]*inv1, acc[mi][ni][3]*inv1);
            }
        }
    }
}

// ============================================================================
extern "C" void kernel_launch(void* const* d_in, const int* in_sizes, int n_in,
                              void* d_out, int out_size) {
    const float* K = (const float*)d_in[0];
    const float* Q = (const float*)d_in[1];
    const float* V = (const float*)d_in[2];
    const float* W = (const float*)d_in[6];
    float* out = (float*)d_out;

    const int SMEM1 = 2*DD*LDH*2 + 512;        // ~70 KB
    const int SMEM3 = 3*DD*LDH*2 + 1024;       // ~105 KB

    cudaFuncSetAttribute(phi_state_kernel, cudaFuncAttributeMaxDynamicSharedMemorySize, SMEM1);
    cudaFuncSetAttribute(output_kernel,    cudaFuncAttributeMaxDynamicSharedMemorySize, SMEM3);

    phi_state_kernel<<<128, 512, SMEM1>>>(K, Q, W, V);
    prefix_kernel<<<256, 256>>>();
    output_kernel<<<128, 512, SMEM3>>>(out);
}

// round 7
// speedup vs baseline: 3.2392x; 1.0678x over previous
#include <cuda_runtime.h>
#include <cuda_fp16.h>
#include <cstdint>

#define BB 4
#define SS 2048
#define DD 128
#define CC 128
#define NCH 16
#define LDH 136       // half-element row stride: 272B rows (16B multiple), conflict-free ldmatrix

// ------------------- scratch (device globals; no allocs allowed) -------------------
__device__ __half g_phiK[BB*SS*DD];      // 2 MB
__device__ __half g_phiQ[BB*SS*DD];      // 2 MB
__device__ __half g_Vth [BB*SS*DD];      // 2 MB  V^T per chunk, half: [(b,ch)][e][t]
__device__ float  g_ScT [BB*NCH*DD*DD];  // 4 MB  fp32 chunk state
__device__ float  g_nc  [BB*NCH*DD];
__device__ __half g_MpTh[BB*NCH*DD*DD];  // 2 MB  exclusive prefix of ScT, half
__device__ float  g_Np  [BB*NCH*DD];

// ------------------- helpers -------------------
__device__ __forceinline__ uint32_t sptr(const void* p){
    return (uint32_t)__cvta_generic_to_shared(p);
}

#define MMA16(d, a, b0v, b1v) \
    asm volatile("mma.sync.aligned.m16n8k16.row.col.f32.f16.f16.f32 " \
        "{%0,%1,%2,%3},{%4,%5,%6,%7},{%8,%9},{%0,%1,%2,%3};" \
        : "+f"(d[0]),"+f"(d[1]),"+f"(d[2]),"+f"(d[3]) \
        : "r"(a[0]),"r"(a[1]),"r"(a[2]),"r"(a[3]),"r"(b0v),"r"(b1v))

#define LDSMX4(r, addr) \
    asm volatile("ldmatrix.sync.aligned.m8n8.x4.shared.b16 {%0,%1,%2,%3},[%4];" \
        : "=r"((r)[0]),"=r"((r)[1]),"=r"((r)[2]),"=r"((r)[3]) : "r"(addr))

#define CP_ASYNC16(dst_u32, src_ptr) \
    asm volatile("cp.async.ca.shared.global [%0], [%1], 16;" :: "r"(dst_u32), "l"(src_ptr))
#define CP_COMMIT() asm volatile("cp.async.commit_group;")
#define CP_WAIT(n)  asm volatile("cp.async.wait_group %0;" :: "n"(n))

// per-lane fragment offsets (element units).
// A m16k16 via x4: rows lane&15, k-half lane>>4.
// B n16k16 via x4: 4 matrices (n0,k0)(n0,k8)(n8,k0)(n8,k8) -> regs map to (b0,b1) of ni and ni+1.
#define FRAG_OFFS() \
    const int rowA  = lane & 15;                            \
    const int kofA  = (lane >> 4) * 8;                      \
    const int rowB4 = (lane & 7) + ((lane >> 4) & 1) * 8;   \
    const int kofB4 = ((lane >> 3) & 1) * 8;                \
    const int er    = lane >> 2;                            \
    const int ec    = (lane & 3) * 2;

#define LOADA2(dst, u, r0, k0) { \
    LDSMX4(dst[0], (u) + (uint32_t)((((r0) + rowA)*LDH + (k0) + kofA) << 1)); \
    LDSMX4(dst[1], (u) + (uint32_t)((((r0) + 16 + rowA)*LDH + (k0) + kofA) << 1)); }

// 32 n-rows (4 n8 fragments) in 2 ldmatrix.x4
#define LOADB32(dst8, u, n0, k0) { \
    LDSMX4((dst8),     (u) + (uint32_t)((((n0) + rowB4)*LDH + (k0) + kofB4) << 1)); \
    LDSMX4((dst8) + 4, (u) + (uint32_t)((((n0) + 16 + rowB4)*LDH + (k0) + kofB4) << 1)); }

// 16 n-rows (2 n8 fragments) in 1 ldmatrix.x4
#define LOADB16(dst4, u, n0, k0) \
    LDSMX4((dst4), (u) + (uint32_t)((((n0) + rowB4)*LDH + (k0) + kofB4) << 1));

// pipelined 128-k GEMM, 32x32 warp tile (acc[2][4][4])
#define GEMM_PIPE_24(acc, uA_, rA0, uB_, nB0) { \
    uint32_t a_[2][2][4]; uint32_t b_[2][8]; \
    LOADA2(a_[0], uA_, rA0, 0); LOADB32(b_[0], uB_, nB0, 0); \
    _Pragma("unroll") \
    for (int kk = 0; kk < 8; ++kk) { \
        const int cur = kk & 1, nxt = cur ^ 1; \
        if (kk < 7) { LOADA2(a_[nxt], uA_, rA0, (kk+1)*16); LOADB32(b_[nxt], uB_, nB0, (kk+1)*16); } \
        _Pragma("unroll") \
        for (int mi = 0; mi < 2; ++mi) \
            _Pragma("unroll") \
            for (int ni = 0; ni < 4; ++ni) \
                MMA16(acc[mi][ni], a_[cur][mi], b_[cur][2*ni], b_[cur][2*ni+1]); \
    } }

// ============================================================================
// Kernel 1 (fused): phi for K & Q; K-blocks additionally compute chunk state
// grid = 128 (64 tiles x {K,Q}), 512 threads, warp tile 32x32
// ============================================================================
__global__ void __launch_bounds__(512, 1)
phi_state_kernel(const float* __restrict__ K, const float* __restrict__ Q,
                 const float* __restrict__ W, const float* __restrict__ V) {
    extern __shared__ char smraw[];
    __half* Xs    = (__half*)smraw;            // [128][LDH]  (later: phiK^T)
    __half* Ws    = Xs + DD*LDH;               // [128][LDH]  (later: V^T)
    float*  scale = (float*)(Ws + DD*LDH);     // [128]

    const int tid  = threadIdx.x;
    const int lane = tid & 31;
    const int wid  = tid >> 5;
    const int tileIdx = blockIdx.x & 63;
    const int sel     = blockIdx.x >> 6;
    const float* src  = sel ? Q : K;
    __half*      dst  = sel ? g_phiQ : g_phiK;
    const float* Xg   = src + (size_t)tileIdx * 128 * DD;

    if (tid < 128) scale[tid] = 0.f;
    __syncthreads();

    #pragma unroll
    for (int it = 0; it < 8; ++it) {
        int i = tid + it*512;
        int t = i >> 5, d4 = i & 31;
        float4 v = reinterpret_cast<const float4*>(Xg)[t*32 + d4];
        float ls = v.x*v.x + v.y*v.y + v.z*v.z + v.w*v.w;
        ls += __shfl_xor_sync(~0u, ls, 16);
        ls += __shfl_xor_sync(~0u, ls, 8);
        ls += __shfl_xor_sync(~0u, ls, 4);
        ls += __shfl_xor_sync(~0u, ls, 2);
        ls += __shfl_xor_sync(~0u, ls, 1);
        if (lane == 0) atomicAdd(&scale[t], ls);
        *reinterpret_cast<__half2*>(Xs + t*LDH + d4*4)     = __floats2half2_rn(v.x, v.y);
        *reinterpret_cast<__half2*>(Xs + t*LDH + d4*4 + 2) = __floats2half2_rn(v.z, v.w);
        float4 w = reinterpret_cast<const float4*>(W)[t*32 + d4];
        *reinterpret_cast<__half2*>(Ws + t*LDH + d4*4)     = __floats2half2_rn(w.x, w.y);
        *reinterpret_cast<__half2*>(Ws + t*LDH + d4*4 + 2) = __floats2half2_rn(w.z, w.w);
    }
    __syncthreads();
    if (tid < 128)
        scale[tid] = __expf(-0.5f * sqrtf(scale[tid])) * 0.08838834764831845f;

    // K blocks: prefetch V into registers; latency hides under GEMM1
    const float* Vg = V + (size_t)tileIdx*CC*DD;
    float4 vreg[8];
    if (sel == 0) {
        #pragma unroll
        for (int it = 0; it < 8; ++it) {
            int i = tid + it*512;
            vreg[it] = reinterpret_cast<const float4*>(Vg)[(i & 127)*32 + (i >> 7)];
        }
    }
    __syncthreads();

    const int wm0 = (wid >> 2) * 32;
    const int wn0 = (wid & 3) * 32;
    FRAG_OFFS();
    const uint32_t uX = sptr(Xs), uW = sptr(Ws);

    float acc[2][4][4];
    #pragma unroll
    for (int mi = 0; mi < 2; ++mi)
        #pragma unroll
        for (int ni = 0; ni < 4; ++ni)
            #pragma unroll
            for (int q = 0; q < 4; ++q) acc[mi][ni][q] = 0.f;

    GEMM_PIPE_24(acc, uX, wm0, uW, wn0);

    __half2 oph[2][4][2];
    #pragma unroll
    for (int mi = 0; mi < 2; ++mi) {
        int r0 = wm0 + mi*16 + er;
        float s0 = scale[r0], s1 = scale[r0 + 8];
        #pragma unroll
        for (int ni = 0; ni < 4; ++ni) {
            oph[mi][ni][0] = __floats2half2_rn(s0*__expf(acc[mi][ni][0]), s0*__expf(acc[mi][ni][1]));
            oph[mi][ni][1] = __floats2half2_rn(s1*__expf(acc[mi][ni][2]), s1*__expf(acc[mi][ni][3]));
        }
    }
    __syncthreads();   // all warps done reading Xs/Ws

    // write phi to gmem
    #pragma unroll
    for (int mi = 0; mi < 2; ++mi) {
        int r0 = wm0 + mi*16 + er;
        size_t g0 = ((size_t)tileIdx*128 + r0) * DD;
        #pragma unroll
        for (int ni = 0; ni < 4; ++ni) {
            int col = wn0 + ni*8 + ec;
            *reinterpret_cast<__half2*>(dst + g0 + col)        = oph[mi][ni][0];
            *reinterpret_cast<__half2*>(dst + g0 + 8*DD + col) = oph[mi][ni][1];
        }
    }

    if (sel == 0) {
        // phiK^T -> Xs
        #pragma unroll
        for (int mi = 0; mi < 2; ++mi) {
            int t0 = wm0 + mi*16 + er;
            #pragma unroll
            for (int ni = 0; ni < 4; ++ni) {
                int col = wn0 + ni*8 + ec;
                Xs[(col  )*LDH + t0]     = oph[mi][ni][0].x;
                Xs[(col+1)*LDH + t0]     = oph[mi][ni][0].y;
                Xs[(col  )*LDH + t0 + 8] = oph[mi][ni][1].x;
                Xs[(col+1)*LDH + t0 + 8] = oph[mi][ni][1].y;
            }
        }
        // V^T -> Ws (from registers) + gmem half copy
        __half* Vthg = g_Vth + (size_t)tileIdx*CC*DD;
        #pragma unroll
        for (int it = 0; it < 8; ++it) {
            int i = tid + it*512;
            int t = i & 127, d4 = i >> 7;
            float4 v = vreg[it];
            __half h0 = __float2half_rn(v.x), h1 = __float2half_rn(v.y);
            __half h2 = __float2half_rn(v.z), h3 = __float2half_rn(v.w);
            Ws[(d4*4+0)*LDH + t] = h0;
            Ws[(d4*4+1)*LDH + t] = h1;
            Ws[(d4*4+2)*LDH + t] = h2;
            Ws[(d4*4+3)*LDH + t] = h3;
            Vthg[(d4*4+0)*128 + t] = h0;
            Vthg[(d4*4+1)*128 + t] = h1;
            Vthg[(d4*4+2)*128 + t] = h2;
            Vthg[(d4*4+3)*128 + t] = h3;
        }
        __syncthreads();

        // GEMM2: ScT[e][d] = sum_t Vt[e][t] * phiKt[d][t]
        float acc2[2][4][4];
        #pragma unroll
        for (int mi = 0; mi < 2; ++mi)
            #pragma unroll
            for (int ni = 0; ni < 4; ++ni)
                #pragma unroll
                for (int q = 0; q < 4; ++q) acc2[mi][ni][q] = 0.f;

        GEMM_PIPE_24(acc2, uW, wm0, uX, wn0);

        float* Sg = g_ScT + (size_t)tileIdx*DD*DD;
        #pragma unroll
        for (int mi = 0; mi < 2; ++mi) {
            int r0 = wm0 + mi*16 + er;
            #pragma unroll
            for (int ni = 0; ni < 4; ++ni) {
                int col = wn0 + ni*8 + ec;
                *reinterpret_cast<float2*>(Sg + (size_t)r0*DD + col)     = make_float2(acc2[mi][ni][0], acc2[mi][ni][1]);
                *reinterpret_cast<float2*>(Sg + (size_t)(r0+8)*DD + col) = make_float2(acc2[mi][ni][2], acc2[mi][ni][3]);
            }
        }

        if (tid < 128) {
            float s = 0.f;
            #pragma unroll 8
            for (int t = 0; t < 128; ++t) s += __half2float(Xs[tid*LDH + t]);
            g_nc[(size_t)tileIdx*DD + tid] = s;
        }
    }
}

// ============================================================================
// Kernel 2: exclusive prefix over chunks (fp32 accum), emit half MpT.
// grid = 256, 256 threads
// ============================================================================
__global__ void prefix_kernel() {
    const int b = blockIdx.x >> 6, slab = blockIdx.x & 63;
    const size_t base = (size_t)b*NCH*DD*DD;
    const int e0 = slab*256 + threadIdx.x;
    float acc = 0.f;
    for (int c = 0; c < NCH; ++c) {
        size_t off = base + (size_t)c*DD*DD;
        g_MpTh[off + e0] = __float2half_rn(acc);
        acc += g_ScT[off + e0];
    }
    if (slab == 0 && threadIdx.x < 128) {
        float an = 0.f;
        int i = threadIdx.x;
        for (int c = 0; c < NCH; ++c) {
            g_Np[(size_t)(b*NCH + c)*DD + i] = an;
            an += g_nc[(size_t)(b*NCH + c)*DD + i];
        }
    }
}

// ============================================================================
// Kernel 3: per-chunk output, split on output columns.
// grid = 128 (64 chunks x 2 j-halves), 512 threads
// All tiles prefetched via cp.async at entry (2 groups).
// ============================================================================
__global__ void __launch_bounds__(512, 1)
output_kernel(float* __restrict__ out) {
    extern __shared__ char smraw[];
    __half* Qs = (__half*)smraw;         // [128][LDH] phiQ
    __half* Bs = Qs + DD*LDH;            // [128][LDH] phiK
    __half* As = Bs + DD*LDH;            // [128][LDH] masked A [t][s]
    __half* Ms = As + DD*LDH;            // [64][LDH]  Mp half-tile
    __half* Vs = Ms + 64*LDH;            // [64][LDH]  V^T half-tile
    float*  rs = (float*)(Vs + 64*LDH);  // [128]
    float*  Np = rs + 128;               // [128]

    const int tid = threadIdx.x, lane = tid & 31, wid = tid >> 5;
    const int chunk = blockIdx.x >> 1, h = blockIdx.x & 1;
    const int b = chunk / NCH, ch = chunk % NCH;
    const int j0h = h * 64;

    const __half* Qg = g_phiQ + (size_t)chunk*CC*DD;
    const __half* Kg = g_phiK + (size_t)chunk*CC*DD;
    const __half* Mg = g_MpTh + (size_t)chunk*DD*DD + (size_t)j0h*DD;
    const __half* Vg = g_Vth  + (size_t)chunk*CC*DD + (size_t)j0h*DD;

    const uint32_t uQ = sptr(Qs), uB = sptr(Bs), uA = sptr(As);
    const uint32_t uM = sptr(Ms), uV = sptr(Vs);

    // group 0: Q + K tiles
    #pragma unroll
    for (int it = 0; it < 4; ++it) {
        int i = tid + it*512;
        int t = i >> 4, c8 = i & 15;
        CP_ASYNC16(uQ + t*(LDH*2) + c8*16, Qg + t*128 + c8*8);
        CP_ASYNC16(uB + t*(LDH*2) + c8*16, Kg + t*128 + c8*8);
    }
    CP_COMMIT();
    // group 1: Mp + V^T tiles
    #pragma unroll
    for (int it = 0; it < 2; ++it) {
        int i = tid + it*512;
        int e = i >> 4, c8 = i & 15;
        CP_ASYNC16(uM + e*(LDH*2) + c8*16, Mg + e*128 + c8*8);
        CP_ASYNC16(uV + e*(LDH*2) + c8*16, Vg + e*128 + c8*8);
    }
    CP_COMMIT();

    if (tid < 128) {
        rs[tid] = 0.f;
        Np[tid] = g_Np[(size_t)chunk*DD + tid];
    }
    CP_WAIT(1);          // Q/K resident
    __syncthreads();

    const int wm0 = (wid >> 2) * 32;
    FRAG_OFFS();

    // ---- Phase A: A[t][s] = phiQ . phiK (128x128), masked half store ----
    {
        const int wn0 = (wid & 3) * 32;
        float acc[2][4][4];
        #pragma unroll
        for (int mi = 0; mi < 2; ++mi)
            #pragma unroll
            for (int ni = 0; ni < 4; ++ni)
                #pragma unroll
                for (int q = 0; q < 4; ++q) acc[mi][ni][q] = 0.f;

        GEMM_PIPE_24(acc, uQ, wm0, uB, wn0);

        #pragma unroll
        for (int mi = 0; mi < 2; ++mi) {
            int t0 = wm0 + mi*16 + er;
            int t1 = t0 + 8;
            #pragma unroll
            for (int ni = 0; ni < 4; ++ni) {
                int s0 = wn0 + ni*8 + ec;
                float v0 = (s0     <= t0) ? acc[mi][ni][0] : 0.f;
                float v1 = (s0 + 1 <= t0) ? acc[mi][ni][1] : 0.f;
                float v2 = (s0     <= t1) ? acc[mi][ni][2] : 0.f;
                float v3 = (s0 + 1 <= t1) ? acc[mi][ni][3] : 0.f;
                *reinterpret_cast<__half2*>(As + t0*LDH + s0) = __floats2half2_rn(v0, v1);
                *reinterpret_cast<__half2*>(As + t1*LDH + s0) = __floats2half2_rn(v2, v3);
            }
        }
    }
    __syncthreads();

    // ---- denominators (4 partial groups) ----
    {
        int t = tid & 127, p = tid >> 7;       // p = 0..3
        float r = 0.f;
        const int s0 = p * 32;
        #pragma unroll 8
        for (int s = s0; s < s0 + 32; s += 2) {
            float2 f = __half22float2(*reinterpret_cast<__half2*>(As + t*LDH + s));
            r += f.x + f.y;
        }
        #pragma unroll 8
        for (int d = s0; d < s0 + 32; ++d)
            r = fmaf(__half2float(Qs[t*LDH + d]), Np[d], r);
        atomicAdd(&rs[t], r);
    }
    CP_WAIT(0);          // Mp/V resident
    __syncthreads();

    // ---- Phase B+C: C = phiQ @ Mp^T + A_masked @ V^T (128 x 64) ----
    {
        const int wn0 = (wid & 3) * 16;
        float acc[2][2][4];
        #pragma unroll
        for (int mi = 0; mi < 2; ++mi)
            #pragma unroll
            for (int ni = 0; ni < 2; ++ni)
                #pragma unroll
                for (int q = 0; q < 4; ++q) acc[mi][ni][q] = 0.f;

        uint32_t a_[2][2][4]; uint32_t b_[2][4];
        LOADA2(a_[0], uQ, wm0, 0);
        LOADB16(b_[0], uM, wn0, 0);
        #pragma unroll
        for (int kk = 0; kk < 16; ++kk) {
            const int cur = kk & 1, nxt = cur ^ 1;
            const int k1 = kk + 1;
            if (k1 < 8) {
                LOADA2(a_[nxt], uQ, wm0, k1*16);
                LOADB16(b_[nxt], uM, wn0, k1*16);
            } else if (k1 < 16) {
                LOADA2(a_[nxt], uA, wm0, (k1-8)*16);
                LOADB16(b_[nxt], uV, wn0, (k1-8)*16);
            }
            #pragma unroll
            for (int mi = 0; mi < 2; ++mi)
                #pragma unroll
                for (int ni = 0; ni < 2; ++ni)
                    MMA16(acc[mi][ni], a_[cur][mi], b_[cur][2*ni], b_[cur][2*ni+1]);
        }

        #pragma unroll
        for (int mi = 0; mi < 2; ++mi) {
            int t0 = wm0 + mi*16 + er;
            float r0 = rs[t0];
            float inv0 = 1.f / (r0 + (r0 > 0.f ? 1e-6f : (r0 < 0.f ? -1e-6f : 0.f)));
            float r1 = rs[t0 + 8];
            float inv1 = 1.f / (r1 + (r1 > 0.f ? 1e-6f : (r1 < 0.f ? -1e-6f : 0.f)));
            size_t row0 = (size_t)b*SS + (size_t)ch*CC + t0;
            #pragma unroll
            for (int ni = 0; ni < 2; ++ni) {
                int col = j0h + wn0 + ni*8 + ec;
                *reinterpret_cast<float2*>(out + row0*DD + col) =
                    make_float2(acc[mi][ni][0]*inv0, acc[mi][ni][1]*inv0);
                *reinterpret_cast<float2*>(out + (row0 + 8)*DD + col) =
                    make_float2(acc[mi][ni][2]*inv1, acc[mi][ni][3]*inv1);
            }
        }
    }
}

// ============================================================================
extern "C" void kernel_launch(void* const* d_in, const int* in_sizes, int n_in,
                              void* d_out, int out_size) {
    const float* K = (const float*)d_in[0];
    const float* Q = (const float*)d_in[1];
    const float* V = (const float*)d_in[2];
    const float* W = (const float*)d_in[6];
    float* out = (float*)d_out;

    const int SMEM1 = 2*DD*LDH*2 + 512;                  // ~70 KB
    const int SMEM3 = 3*DD*LDH*2 + 2*64*LDH*2 + 1024;    // ~141 KB

    cudaFuncSetAttribute(phi_state_kernel, cudaFuncAttributeMaxDynamicSharedMemorySize, SMEM1);
    cudaFuncSetAttribute(output_kernel,    cudaFuncAttributeMaxDynamicSharedMemorySize, SMEM3);

    phi_state_kernel<<<128, 512, SMEM1>>>(K, Q, W, V);
    prefix_kernel<<<256, 256>>>();
    output_kernel<<<128, 512, SMEM3>>>(out);
}